// round 11
// baseline (speedup 1.0000x reference)
#include <cuda_runtime.h>
#include <cuda_fp16.h>
#include <math.h>
#include <stdint.h>

#define B_    2
#define S_    4096
#define D_    2048
#define H_    16
#define DK_   128
#define DV_   128
#define SEG_  512
#define NSEG_ 8
#define DH_   8192
#define M_    (B_*S_)   // 8192 rows

// ---------------- scratch (device globals; no allocation allowed) ----------------
__device__ __align__(16) float g_y  [M_ * D_];
__device__ __align__(16) float g_U2 [512 * DK_ * DV_];     // half-segment partials
__device__ __align__(16) float g_zU2[512 * DK_];
__device__ __align__(16) float g_mem[B_*H_*NSEG_ * DK_ * DV_];
__device__ __align__(16) float g_z  [B_*H_*NSEG_ * DK_];
// fp16 tensors
__device__ __align__(16) __half g_x  [M_ * D_];
__device__ __align__(16) __half g_wq [D_ * D_];
__device__ __align__(16) __half g_wk [D_ * D_];
__device__ __align__(16) __half g_wv [D_ * D_];
__device__ __align__(16) __half g_wo [D_ * D_];
__device__ __align__(16) __half g_w1 [D_ * DH_];
__device__ __align__(16) __half g_w2 [DH_ * D_];
__device__ __align__(16) __half g_q  [M_ * D_];
__device__ __align__(16) __half g_k  [M_ * D_];
__device__ __align__(16) __half g_v  [M_ * D_];
__device__ __align__(16) __half g_atd[M_ * D_];   // att_dot (fp16)
__device__ __align__(16) __half g_at [M_ * D_];   // combined att
__device__ __align__(16) __half g_ao [M_ * D_];
__device__ __align__(16) __half g_hh [(size_t)M_ * DH_];

__device__ __forceinline__ float elu1(float x) { return x > 0.f ? x + 1.f : __expf(x); }

__device__ __forceinline__ uint32_t packh2(float a, float b) {
    __half2 h = __floats2half2_rn(a, b);
    return *(uint32_t*)&h;
}

// ================= mma helpers ===================================================
__device__ __forceinline__ void cp16(void* dst, const void* src) {
    uint32_t d = (uint32_t)__cvta_generic_to_shared(dst);
    asm volatile("cp.async.cg.shared.global [%0], [%1], 16;" :: "r"(d), "l"(src));
}

#define LDSM4(f, p) do { \
    uint32_t a_ = (uint32_t)__cvta_generic_to_shared(p); \
    asm volatile("ldmatrix.sync.aligned.m8n8.x4.shared.b16 {%0,%1,%2,%3}, [%4];" \
        : "=r"(f[0]), "=r"(f[1]), "=r"(f[2]), "=r"(f[3]) : "r"(a_)); \
} while (0)

#define LDSM4T(f, p) do { \
    uint32_t a_ = (uint32_t)__cvta_generic_to_shared(p); \
    asm volatile("ldmatrix.sync.aligned.m8n8.x4.trans.shared.b16 {%0,%1,%2,%3}, [%4];" \
        : "=r"(f[0]), "=r"(f[1]), "=r"(f[2]), "=r"(f[3]) : "r"(a_)); \
} while (0)

#define MMAH(d, a, b0, b1) \
    asm volatile("mma.sync.aligned.m16n8k16.row.col.f32.f16.f16.f32 " \
        "{%0,%1,%2,%3}, {%4,%5,%6,%7}, {%8,%9}, {%0,%1,%2,%3};" \
        : "+f"(d[0]), "+f"(d[1]), "+f"(d[2]), "+f"(d[3]) \
        : "r"(a[0]), "r"(a[1]), "r"(a[2]), "r"(a[3]), "r"(b0), "r"(b1))

// ================= fp16 tensor-core GEMM, CTA 128x128, warp 32x64 ================
#define SA_STRIDE 40
#define SB_STRIDE 136
#define SA_STAGE  (128*SA_STRIDE)
#define SB_STAGE  (32*SB_STRIDE)
#define HG_SMEM ((SA_STAGE + SB_STAGE) * 2 * 2)

__device__ __forceinline__ void hg_load_stage(
    const __half* __restrict__ Ag, const __half* __restrict__ Bg,
    __half* sA, __half* sB, int tid, size_t m0, size_t n0, int Kk, int Nn, int k0)
{
#pragma unroll
    for (int it = 0; it < 2; it++) {
        int c = it*256 + tid;
        int r = c >> 2, col = (c & 3) << 3;
        cp16(sA + r * SA_STRIDE + col, Ag + (m0 + r) * (size_t)Kk + k0 + col);
    }
#pragma unroll
    for (int it = 0; it < 2; it++) {
        int c = it*256 + tid;
        int r = c >> 4, col = (c & 15) << 3;
        cp16(sB + r * SB_STRIDE + col, Bg + (size_t)(k0 + r) * Nn + n0 + col);
    }
    asm volatile("cp.async.commit_group;");
}

__global__ void __launch_bounds__(256)
hgemm_kernel(const __half* __restrict__ Ag, const __half* __restrict__ Bg,
             int Kk, int Nn,
             const float* __restrict__ bias, int relu, const float* __restrict__ resid,
             float* __restrict__ C, __half* __restrict__ Ch)
{
    extern __shared__ __half smem[];
    __half* sA = smem;
    __half* sB = smem + 2*SA_STAGE;

    int tid = threadIdx.x;
    int warp = tid >> 5, lane = tid & 31;
    int wm = warp >> 1, wn = warp & 1;
    size_t m0 = (size_t)blockIdx.y * 128;
    size_t n0 = (size_t)blockIdx.x * 128;

    float acc[2][8][4];
#pragma unroll
    for (int i = 0; i < 2; i++)
#pragma unroll
        for (int j = 0; j < 8; j++)
#pragma unroll
            for (int t = 0; t < 4; t++) acc[i][j][t] = 0.f;

    int nk = Kk >> 5;
    hg_load_stage(Ag, Bg, sA, sB, tid, m0, n0, Kk, Nn, 0);

    for (int kt = 0; kt < nk; kt++) {
        int cur = kt & 1;
        if (kt + 1 < nk) {
            hg_load_stage(Ag, Bg, sA + ((kt+1)&1)*SA_STAGE, sB + ((kt+1)&1)*SB_STAGE,
                          tid, m0, n0, Kk, Nn, (kt+1)*32);
            asm volatile("cp.async.wait_group 1;");
        } else {
            asm volatile("cp.async.wait_group 0;");
        }
        __syncthreads();

        __half* a = sA + cur*SA_STAGE;
        __half* bb = sB + cur*SB_STAGE;

#pragma unroll
        for (int k16 = 0; k16 < 32; k16 += 16) {
            uint32_t af[2][4], bf[4][4];
#pragma unroll
            for (int mi = 0; mi < 2; mi++)
                LDSM4(af[mi], a + (size_t)(wm*32 + mi*16 + (lane & 15)) * SA_STRIDE
                                + k16 + (lane >> 4) * 8);
#pragma unroll
            for (int nb = 0; nb < 4; nb++)
                LDSM4T(bf[nb], bb + (size_t)(k16 + (lane & 15)) * SB_STRIDE
                                  + wn*64 + nb*16 + (lane >> 4) * 8);
#pragma unroll
            for (int mi = 0; mi < 2; mi++)
#pragma unroll
                for (int ni = 0; ni < 8; ni++) {
                    int nb = ni >> 1, sel = (ni & 1) * 2;
                    MMAH(acc[mi][ni], af[mi], bf[nb][sel], bf[nb][sel+1]);
                }
        }
        __syncthreads();
    }

#pragma unroll
    for (int mi = 0; mi < 2; mi++)
#pragma unroll
        for (int ni = 0; ni < 8; ni++) {
            int col = wn*64 + ni*8 + (lane & 3) * 2;
#pragma unroll
            for (int hh = 0; hh < 2; hh++) {
                int row = wm*32 + mi*16 + (lane >> 2) + hh*8;
                float v0 = acc[mi][ni][hh*2], v1 = acc[mi][ni][hh*2+1];
                size_t o = (m0 + row) * (size_t)Nn + n0 + col;
                if (bias) { v0 += bias[n0+col]; v1 += bias[n0+col+1]; }
                if (resid) { v0 += resid[o]; v1 += resid[o+1]; }
                if (relu) { v0 = fmaxf(v0, 0.f); v1 = fmaxf(v1, 0.f); }
                if (C) { C[o] = v0; C[o+1] = v1; }
                if (Ch) *(uint32_t*)(Ch + o) = packh2(v0, v1);
            }
        }
}

// ---------------- fp32 -> fp16 converts ----------------------------------------
__global__ void __launch_bounds__(256)
cvt_kernel(const float4* __restrict__ in, __half2* __restrict__ out, int nquads)
{
    int i = blockIdx.x * 256 + threadIdx.x;
    if (i >= nquads) return;
    float4 v = in[i];
    out[2*i]   = __floats2half2_rn(v.x, v.y);
    out[2*i+1] = __floats2half2_rn(v.z, v.w);
}

__global__ void __launch_bounds__(256)
cvt3_kernel(const float4* __restrict__ a, const float4* __restrict__ b,
            const float4* __restrict__ c,
            __half2* __restrict__ oa, __half2* __restrict__ ob,
            __half2* __restrict__ oc, int nquads)
{
    int i = blockIdx.x * 256 + threadIdx.x;
    if (i >= nquads) return;
    const float4* in = (blockIdx.y == 0) ? a : (blockIdx.y == 1 ? b : c);
    __half2* out     = (blockIdx.y == 0) ? oa : (blockIdx.y == 1 ? ob : oc);
    float4 v = in[i];
    out[2*i]   = __floats2half2_rn(v.x, v.y);
    out[2*i+1] = __floats2half2_rn(v.z, v.w);
}

// ================= flash attention (fp16 mma, cp.async double-buffered) ==========
#define AT_STR 136
#define AT_TILE (64*AT_STR)                 // 8704 halfs
#define AT_STAGE (2*AT_TILE)                // K tile + V tile
#define ATTN_SMEM_BYTES ((AT_TILE + 2*AT_STAGE) * 2)   // 87040 B

__device__ __forceinline__ void attn_load_kv(
    const __half* __restrict__ k, const __half* __restrict__ v,
    __half* stK, __half* stV, size_t base, int kt, int tid)
{
#pragma unroll
    for (int it = 0; it < 8; it++) {
        int e = it*128 + tid, r = e >> 4, c8 = (e & 15) << 3;
        size_t go = base + (size_t)(kt*64 + r)*2048 + c8;
        cp16(stK + r*AT_STR + c8, k + go);
        cp16(stV + r*AT_STR + c8, v + go);
    }
    asm volatile("cp.async.commit_group;");
}

__global__ void __launch_bounds__(128)
attn_mma_kernel(const __half* __restrict__ q, const __half* __restrict__ k,
                const __half* __restrict__ v, __half* __restrict__ atd)
{
    extern __shared__ __half sm[];
    __half* Qs = sm;                         // [64][136]
    __half* St = sm + AT_TILE;               // 2 stages of (K,V)

    int qt = blockIdx.x, seg = blockIdx.y, bh = blockIdx.z;
    int b = bh >> 4, h = bh & 15;
    int tid = threadIdx.x, warp = tid >> 5, lane = tid & 31;
    const float scale = 0.08838834764831845f;
    size_t base = ((size_t)(b*S_ + seg*SEG_) * H_ + h) * DK_;

#pragma unroll
    for (int it = 0; it < 8; it++) {
        int e = it*128 + tid, r = e >> 4, c8 = (e & 15) << 3;
        size_t go = base + (size_t)(qt*64 + r)*2048 + c8;
        *(uint4*)(Qs + r*AT_STR + c8) = *(const uint4*)(q + go);
    }

    float o[16][4];
#pragma unroll
    for (int t = 0; t < 16; t++)
#pragma unroll
        for (int j = 0; j < 4; j++) o[t][j] = 0.f;
    float m0 = -1e30f, m1 = -1e30f, l0 = 0.f, l1 = 0.f;
    int r0g = qt*64 + warp*16 + (lane >> 2);
    int r1g = r0g + 8;

    attn_load_kv(k, v, St, St + AT_TILE, base, 0, tid);

    for (int kt = 0; kt <= qt; kt++) {
        if (kt < qt) {
            __half* nx = St + ((kt+1)&1)*AT_STAGE;
            attn_load_kv(k, v, nx, nx + AT_TILE, base, kt+1, tid);
            asm volatile("cp.async.wait_group 1;");
        } else {
            asm volatile("cp.async.wait_group 0;");
        }
        __syncthreads();

        __half* Ks = St + (kt&1)*AT_STAGE;
        __half* Vs = Ks + AT_TILE;

        float s[8][4];
#pragma unroll
        for (int t = 0; t < 8; t++)
#pragma unroll
            for (int j = 0; j < 4; j++) s[t][j] = 0.f;

#pragma unroll
        for (int kk = 0; kk < 8; kk++) {
            uint32_t qa[4];
            LDSM4(qa, Qs + (size_t)(warp*16 + (lane & 15))*AT_STR + kk*16 + (lane >> 4)*8);
#pragma unroll
            for (int ng = 0; ng < 4; ng++) {
                uint32_t kf[4];
                LDSM4(kf, Ks + (size_t)(ng*16 + (lane & 15))*AT_STR + kk*16 + (lane >> 4)*8);
                MMAH(s[2*ng],   qa, kf[0], kf[2]);
                MMAH(s[2*ng+1], qa, kf[1], kf[3]);
            }
        }

        float mx0 = -1e30f, mx1 = -1e30f;
#pragma unroll
        for (int t = 0; t < 8; t++) {
            int colb = kt*64 + t*8 + (lane & 3)*2;
            float a0 = s[t][0]*scale, a1 = s[t][1]*scale;
            float a2 = s[t][2]*scale, a3 = s[t][3]*scale;
            if (kt == qt) {
                if (colb     > r0g) a0 = -1e30f;
                if (colb + 1 > r0g) a1 = -1e30f;
                if (colb     > r1g) a2 = -1e30f;
                if (colb + 1 > r1g) a3 = -1e30f;
            }
            s[t][0] = a0; s[t][1] = a1; s[t][2] = a2; s[t][3] = a3;
            mx0 = fmaxf(mx0, fmaxf(a0, a1));
            mx1 = fmaxf(mx1, fmaxf(a2, a3));
        }
        mx0 = fmaxf(mx0, __shfl_xor_sync(0xffffffffu, mx0, 1));
        mx0 = fmaxf(mx0, __shfl_xor_sync(0xffffffffu, mx0, 2));
        mx1 = fmaxf(mx1, __shfl_xor_sync(0xffffffffu, mx1, 1));
        mx1 = fmaxf(mx1, __shfl_xor_sync(0xffffffffu, mx1, 2));
        float m0n = fmaxf(m0, mx0), m1n = fmaxf(m1, mx1);
        float rc0 = __expf(m0 - m0n), rc1 = __expf(m1 - m1n);
        float sum0 = 0.f, sum1 = 0.f;
#pragma unroll
        for (int t = 0; t < 8; t++) {
            s[t][0] = __expf(s[t][0] - m0n); sum0 += s[t][0];
            s[t][1] = __expf(s[t][1] - m0n); sum0 += s[t][1];
            s[t][2] = __expf(s[t][2] - m1n); sum1 += s[t][2];
            s[t][3] = __expf(s[t][3] - m1n); sum1 += s[t][3];
        }
        sum0 += __shfl_xor_sync(0xffffffffu, sum0, 1);
        sum0 += __shfl_xor_sync(0xffffffffu, sum0, 2);
        sum1 += __shfl_xor_sync(0xffffffffu, sum1, 1);
        sum1 += __shfl_xor_sync(0xffffffffu, sum1, 2);
        l0 = l0*rc0 + sum0;  l1 = l1*rc1 + sum1;
        m0 = m0n;  m1 = m1n;
#pragma unroll
        for (int t = 0; t < 16; t++) {
            o[t][0] *= rc0; o[t][1] *= rc0; o[t][2] *= rc1; o[t][3] *= rc1;
        }

#pragma unroll
        for (int kk = 0; kk < 4; kk++) {
            uint32_t ah[4];
            ah[0] = packh2(s[2*kk][0],   s[2*kk][1]);
            ah[1] = packh2(s[2*kk][2],   s[2*kk][3]);
            ah[2] = packh2(s[2*kk+1][0], s[2*kk+1][1]);
            ah[3] = packh2(s[2*kk+1][2], s[2*kk+1][3]);
#pragma unroll
            for (int dg = 0; dg < 8; dg++) {
                uint32_t vf[4];
                LDSM4T(vf, Vs + (size_t)(kk*16 + (lane & 15))*AT_STR + dg*16 + (lane >> 4)*8);
                MMAH(o[2*dg],   ah, vf[0], vf[1]);
                MMAH(o[2*dg+1], ah, vf[2], vf[3]);
            }
        }
        __syncthreads();
    }

    float inv0 = 1.f / l0, inv1 = 1.f / l1;
#pragma unroll
    for (int t = 0; t < 16; t++) {
        size_t ro = base + (size_t)(qt*64 + warp*16 + (lane >> 2))*2048 + t*8 + (lane & 3)*2;
        *(uint32_t*)(atd + ro)          = packh2(o[t][0]*inv0, o[t][1]*inv0);
        *(uint32_t*)(atd + ro + 8*2048) = packh2(o[t][2]*inv1, o[t][3]*inv1);
    }
}

// ================= memory update: U = sig(K)^T V over HALF segments ==============
// grid 512 = bh*16 + hseg (256 rows each)
#define MU_KSTR 72
#define MU_KTILE (128*MU_KSTR)
#define MU_VSTR 136
#define MU_VTILE (64*MU_VSTR)
#define MEMUPD_SMEM ((MU_KTILE + MU_VTILE) * 2)

__global__ void __launch_bounds__(256)
memupd_mma_kernel(const __half* __restrict__ k, const __half* __restrict__ v,
                  float* __restrict__ U2, float* __restrict__ zU2)
{
    extern __shared__ __half sm[];
    __half* sK = sm;                    // [dk 128][s 64] transposed
    __half* sV = sm + MU_KTILE;         // [s 64][dv 128]
    __shared__ float zsm[128];

    int hseg = blockIdx.x & 15, bhx = blockIdx.x >> 4;
    int b = bhx >> 4, h = bhx & 15;
    int tid = threadIdx.x, warp = tid >> 5, lane = tid & 31;
    int wm = warp >> 1, wn = warp & 1;
    size_t base = ((size_t)(b*S_ + hseg*256) * H_ + h) * DK_;

    if (tid < 128) zsm[tid] = 0.f;

    float acc[2][8][4];
#pragma unroll
    for (int i = 0; i < 2; i++)
#pragma unroll
        for (int j = 0; j < 8; j++)
#pragma unroll
            for (int t = 0; t < 4; t++) acc[i][j][t] = 0.f;

    for (int st = 0; st < 4; st++) {
        int s0 = st * 64;
#pragma unroll
        for (int it = 0; it < 16; it++) {
            int e = it*256 + tid, s = e >> 6, c2 = e & 63;
            size_t go = base + (size_t)(s0 + s)*2048 + 2*c2;
            __half2 h2 = *(const __half2*)(k + go);
            sK[(2*c2)  *MU_KSTR + s] = __float2half_rn(elu1(__low2float(h2)));
            sK[(2*c2+1)*MU_KSTR + s] = __float2half_rn(elu1(__high2float(h2)));
        }
#pragma unroll
        for (int it = 0; it < 4; it++) {
            int e = it*256 + tid, r = e >> 4, c8 = (e & 15) << 3;
            size_t go = base + (size_t)(s0 + r)*2048 + c8;
            *(uint4*)(sV + r*MU_VSTR + c8) = *(const uint4*)(v + go);
        }
        __syncthreads();

        if (tid < 128) {
            float zz = 0.f;
#pragma unroll 4
            for (int s = 0; s < 64; s++) zz += __half2float(sK[tid*MU_KSTR + s]);
            zsm[tid] += zz;
        }

#pragma unroll
        for (int kk = 0; kk < 4; kk++) {
            uint32_t a[2][4];
#pragma unroll
            for (int mi = 0; mi < 2; mi++)
                LDSM4(a[mi], sK + (size_t)(wm*32 + mi*16 + (lane & 15))*MU_KSTR + kk*16 + (lane >> 4)*8);
#pragma unroll
            for (int ng = 0; ng < 4; ng++) {
                uint32_t bb[4];
                LDSM4T(bb, sV + (size_t)(kk*16 + (lane & 15))*MU_VSTR + wn*64 + ng*16 + (lane >> 4)*8);
#pragma unroll
                for (int mi = 0; mi < 2; mi++) {
                    MMAH(acc[mi][2*ng],   a[mi], bb[0], bb[1]);
                    MMAH(acc[mi][2*ng+1], a[mi], bb[2], bb[3]);
                }
            }
        }
        __syncthreads();
    }

    size_t ob = (size_t)blockIdx.x * (DK_*DV_);
#pragma unroll
    for (int mi = 0; mi < 2; mi++)
#pragma unroll
        for (int ni = 0; ni < 8; ni++) {
            int col = wn*64 + ni*8 + (lane & 3)*2;
#pragma unroll
            for (int hh = 0; hh < 2; hh++) {
                int row = wm*32 + mi*16 + (lane >> 2) + hh*8;
                float2 w; w.x = acc[mi][ni][hh*2]; w.y = acc[mi][ni][hh*2+1];
                *(float2*)(U2 + ob + (size_t)row*128 + col) = w;
            }
        }
    if (tid < 128) zU2[(size_t)blockIdx.x*128 + tid] = zsm[tid];
}

// ---------------- exclusive prefix over segments (from half-seg partials) -------
__global__ void __launch_bounds__(256)
prefix_kernel(const float* __restrict__ U2, const float* __restrict__ zU2,
              float* __restrict__ Mem, float* __restrict__ Z)
{
    int bh = blockIdx.x, tid = threadIdx.x;
    for (int idx = tid; idx < DK_*DV_; idx += 256) {
        float run = 0.f;
#pragma unroll
        for (int sg = 0; sg < NSEG_; sg++) {
            Mem[((size_t)(bh*NSEG_ + sg)) * (DK_*DV_) + idx] = run;
            run += U2[((size_t)(bh*16 + 2*sg))   * (DK_*DV_) + idx]
                 + U2[((size_t)(bh*16 + 2*sg+1)) * (DK_*DV_) + idx];
        }
    }
    if (tid < 128) {
        float run = 1.f / 128.f;
#pragma unroll
        for (int sg = 0; sg < NSEG_; sg++) {
            Z[(size_t)(bh*NSEG_ + sg) * 128 + tid] = run;
            run += zU2[(size_t)(bh*16 + 2*sg)   * 128 + tid]
                 + zU2[(size_t)(bh*16 + 2*sg+1) * 128 + tid];
        }
    }
}

// ================= retrieval + gate combine (fp16 mma) ===========================
#define RT_STR 136
#define RT_TILE (128*RT_STR)
#define RETR_SMEM (2 * RT_TILE * 2)

__global__ void __launch_bounds__(256)
retrieve_mma_kernel(const __half* __restrict__ q, const float* __restrict__ Mem,
                    const float* __restrict__ Z, const float* __restrict__ betas,
                    const __half* __restrict__ atd, __half* __restrict__ at)
{
    extern __shared__ __half sm[];
    __half* Mh = sm;                 // [dk 128][dv 128]
    __half* Sh = sm + RT_TILE;       // sigma(Q) [s 128][dk 128]
    __shared__ float den[128], zz[128], gate[128], denp[256];

    int seg = blockIdx.x & 7, bhx = blockIdx.x >> 3;
    int b = bhx >> 4, h = bhx & 15;
    int tid = threadIdx.x, warp = tid >> 5, lane = tid & 31;
    size_t base = ((size_t)(b*S_ + seg*SEG_) * H_ + h) * DK_;
    size_t mb = (size_t)blockIdx.x * 16384;

    if (tid < 128) {
        gate[tid] = 1.f / (1.f + __expf(-betas[h*128 + tid]));
        zz[tid]   = Z[(size_t)blockIdx.x*128 + tid];
    }
#pragma unroll
    for (int it = 0; it < 16; it++) {
        int e = it*256 + tid, r = e >> 5, c4 = (e & 31) << 2;
        float4 v = *(const float4*)(Mem + mb + (size_t)r*128 + c4);
        *(__half2*)(Mh + r*RT_STR + c4)     = __floats2half2_rn(v.x, v.y);
        *(__half2*)(Mh + r*RT_STR + c4 + 2) = __floats2half2_rn(v.z, v.w);
    }
    __syncthreads();

    for (int ch = 0; ch < 4; ch++) {
        int s0 = ch * 128;
#pragma unroll
        for (int it = 0; it < 32; it++) {
            int e = it*256 + tid, s = e >> 6, c2 = e & 63;
            size_t go = base + (size_t)(s0 + s)*2048 + 2*c2;
            __half2 h2 = *(const __half2*)(q + go);
            *(__half2*)(Sh + s*RT_STR + 2*c2) =
                __floats2half2_rn(elu1(__low2float(h2)), elu1(__high2float(h2)));
        }
        __syncthreads();
        {   // den: 2 threads per row, 64 dk each
            int r = tid >> 1, hf = tid & 1;
            float d = 0.f;
#pragma unroll 4
            for (int dk = hf*64; dk < hf*64 + 64; dk++)
                d += __half2float(Sh[r*RT_STR + dk]) * zz[dk];
            denp[tid] = d;
        }
        __syncthreads();
        if (tid < 128) den[tid] = denp[2*tid] + denp[2*tid+1];
        __syncthreads();

        float o[16][4];
#pragma unroll
        for (int t = 0; t < 16; t++)
#pragma unroll
            for (int j = 0; j < 4; j++) o[t][j] = 0.f;

#pragma unroll
        for (int kk = 0; kk < 8; kk++) {
            uint32_t qa[4];
            LDSM4(qa, Sh + (size_t)(warp*16 + (lane & 15))*RT_STR + kk*16 + (lane >> 4)*8);
#pragma unroll
            for (int ng = 0; ng < 8; ng++) {
                uint32_t mh4[4];
                LDSM4T(mh4, Mh + (size_t)(kk*16 + (lane & 15))*RT_STR + ng*16 + (lane >> 4)*8);
                MMAH(o[2*ng],   qa, mh4[0], mh4[1]);
                MMAH(o[2*ng+1], qa, mh4[2], mh4[3]);
            }
        }

        float inv0 = 1.f / den[warp*16 + (lane >> 2)];
        float inv1 = 1.f / den[warp*16 + (lane >> 2) + 8];
#pragma unroll
        for (int t = 0; t < 16; t++) {
            int col = t*8 + (lane & 3)*2;
            float g0 = gate[col], g1 = gate[col+1];
            size_t ro = base + (size_t)(s0 + warp*16 + (lane >> 2))*2048 + col;
            __half2 d0 = *(const __half2*)(atd + ro);
            __half2 d1 = *(const __half2*)(atd + ro + 8*2048);
            float v0 = g0*(o[t][0]*inv0) + (1.f - g0)*__low2float(d0);
            float v1 = g1*(o[t][1]*inv0) + (1.f - g1)*__high2float(d0);
            float v2 = g0*(o[t][2]*inv1) + (1.f - g0)*__low2float(d1);
            float v3 = g1*(o[t][3]*inv1) + (1.f - g1)*__high2float(d1);
            *(uint32_t*)(at + ro)          = packh2(v0, v1);
            *(uint32_t*)(at + ro + 8*2048) = packh2(v2, v3);
        }
        __syncthreads();
    }
}

// ---------------- LayerNorm -----------------------------------------------------
__global__ void __launch_bounds__(256)
ln_kernel(const float* __restrict__ y, const float* __restrict__ gg,
          const float* __restrict__ bb, float* __restrict__ out)
{
    size_t row = blockIdx.x;
    const float* p = y + row * D_;
    int tid = threadIdx.x;
    float4 v0 = *(const float4*)(p + tid*8);
    float4 v1 = *(const float4*)(p + tid*8 + 4);
    float s  = v0.x+v0.y+v0.z+v0.w + v1.x+v1.y+v1.z+v1.w;
    float s2 = v0.x*v0.x+v0.y*v0.y+v0.z*v0.z+v0.w*v0.w
             + v1.x*v1.x+v1.y*v1.y+v1.z*v1.z+v1.w*v1.w;
#pragma unroll
    for (int o = 16; o >= 1; o >>= 1) {
        s  += __shfl_xor_sync(0xffffffffu, s, o);
        s2 += __shfl_xor_sync(0xffffffffu, s2, o);
    }
    __shared__ float red[16];
    __shared__ float stat[2];
    int warp = tid >> 5, lane = tid & 31;
    if (lane == 0) { red[warp] = s; red[warp + 8] = s2; }
    __syncthreads();
    if (tid == 0) {
        float S = 0.f, S2 = 0.f;
#pragma unroll
        for (int w = 0; w < 8; w++) { S += red[w]; S2 += red[w + 8]; }
        float mean = S / (float)D_;
        float var  = S2 / (float)D_ - mean*mean;
        stat[0] = mean;
        stat[1] = rsqrtf(var + 1e-5f);
    }
    __syncthreads();
    float mean = stat[0], inv = stat[1];
    float4 g0 = *(const float4*)(gg + tid*8), g1 = *(const float4*)(gg + tid*8 + 4);
    float4 b0 = *(const float4*)(bb + tid*8), b1 = *(const float4*)(bb + tid*8 + 4);
    float4 o0, o1;
    o0.x = (v0.x-mean)*inv*g0.x + b0.x; o0.y = (v0.y-mean)*inv*g0.y + b0.y;
    o0.z = (v0.z-mean)*inv*g0.z + b0.z; o0.w = (v0.w-mean)*inv*g0.w + b0.w;
    o1.x = (v1.x-mean)*inv*g1.x + b1.x; o1.y = (v1.y-mean)*inv*g1.y + b1.y;
    o1.z = (v1.z-mean)*inv*g1.z + b1.z; o1.w = (v1.w-mean)*inv*g1.w + b1.w;
    *(float4*)(out + row*D_ + tid*8)     = o0;
    *(float4*)(out + row*D_ + tid*8 + 4) = o1;
}

// ---------------- launch --------------------------------------------------------
static inline void cvt_launch(const float* src, __half* dst, size_t nelems)
{
    int nq = (int)(nelems / 4);
    cvt_kernel<<<(nq + 255)/256, 256>>>((const float4*)src, (__half2*)dst, nq);
}

extern "C" void kernel_launch(void* const* d_in, const int* in_sizes, int n_in,
                              void* d_out, int out_size)
{
    const float* x     = (const float*)d_in[0];
    const float* Wq    = (const float*)d_in[1];
    const float* Wk    = (const float*)d_in[2];
    const float* Wv    = (const float*)d_in[3];
    const float* Wo    = (const float*)d_in[4];
    const float* betas = (const float*)d_in[5];
    const float* W1    = (const float*)d_in[6];
    const float* b1    = (const float*)d_in[7];
    const float* W2    = (const float*)d_in[8];
    const float* b2    = (const float*)d_in[9];
    const float* ln_g  = (const float*)d_in[10];
    const float* ln_b  = (const float*)d_in[11];
    float* out = (float*)d_out;

    float *y_, *U2_, *zU2_, *mem_, *z_;
    cudaGetSymbolAddress((void**)&y_,   g_y);
    cudaGetSymbolAddress((void**)&U2_,  g_U2);
    cudaGetSymbolAddress((void**)&zU2_, g_zU2);
    cudaGetSymbolAddress((void**)&mem_, g_mem);
    cudaGetSymbolAddress((void**)&z_,   g_z);

    __half *xh,*wq,*wk,*wv,*wo,*w1,*w2,*qh,*kh,*vh,*atd,*at,*ao,*hh;
    cudaGetSymbolAddress((void**)&xh,  g_x);
    cudaGetSymbolAddress((void**)&wq,  g_wq);
    cudaGetSymbolAddress((void**)&wk,  g_wk);
    cudaGetSymbolAddress((void**)&wv,  g_wv);
    cudaGetSymbolAddress((void**)&wo,  g_wo);
    cudaGetSymbolAddress((void**)&w1,  g_w1);
    cudaGetSymbolAddress((void**)&w2,  g_w2);
    cudaGetSymbolAddress((void**)&qh,  g_q);
    cudaGetSymbolAddress((void**)&kh,  g_k);
    cudaGetSymbolAddress((void**)&vh,  g_v);
    cudaGetSymbolAddress((void**)&atd, g_atd);
    cudaGetSymbolAddress((void**)&at,  g_at);
    cudaGetSymbolAddress((void**)&ao,  g_ao);
    cudaGetSymbolAddress((void**)&hh,  g_hh);

    cudaFuncSetAttribute(hgemm_kernel,
        cudaFuncAttributeMaxDynamicSharedMemorySize, HG_SMEM);
    cudaFuncSetAttribute(attn_mma_kernel,
        cudaFuncAttributeMaxDynamicSharedMemorySize, ATTN_SMEM_BYTES);
    cudaFuncSetAttribute(memupd_mma_kernel,
        cudaFuncAttributeMaxDynamicSharedMemorySize, MEMUPD_SMEM);
    cudaFuncSetAttribute(retrieve_mma_kernel,
        cudaFuncAttributeMaxDynamicSharedMemorySize, RETR_SMEM);

    dim3 gProj(D_/128, M_/128);          // (16, 64)
    dim3 gMlp1(DH_/128, M_/128);         // (64, 64)

    // launch idx 0..4: converts + QKV GEMMs; idx 5 = attn_mma (ncu -s 5 target)
    cvt_launch(x, xh, (size_t)M_ * D_);                                     // 0
    {
        int nq = (int)((size_t)D_ * D_ / 4);
        cvt3_kernel<<<dim3((nq + 255)/256, 3), 256>>>(                      // 1
            (const float4*)Wq, (const float4*)Wk, (const float4*)Wv,
            (__half2*)wq, (__half2*)wk, (__half2*)wv, nq);
    }
    hgemm_kernel<<<gProj, 256, HG_SMEM>>>(xh, wq, D_, D_, nullptr, 0, nullptr, nullptr, qh); // 2
    hgemm_kernel<<<gProj, 256, HG_SMEM>>>(xh, wk, D_, D_, nullptr, 0, nullptr, nullptr, kh); // 3
    hgemm_kernel<<<gProj, 256, HG_SMEM>>>(xh, wv, D_, D_, nullptr, 0, nullptr, nullptr, vh); // 4

    attn_mma_kernel<<<dim3(8, 8, 32), 128, ATTN_SMEM_BYTES>>>(qh, kh, vh, atd);              // 5
    memupd_mma_kernel<<<512, 256, MEMUPD_SMEM>>>(kh, vh, U2_, zU2_);                         // 6
    prefix_kernel<<<32, 256>>>(U2_, zU2_, mem_, z_);                                         // 7
    cvt_launch(Wo, wo, (size_t)D_ * D_);                                                     // 8
    retrieve_mma_kernel<<<256, 256, RETR_SMEM>>>(qh, mem_, z_, betas, atd, at);              // 9

    hgemm_kernel<<<gProj, 256, HG_SMEM>>>(at, wo, D_, D_, nullptr, 0, nullptr, nullptr, ao); // 10
    cvt_launch(W1, w1, (size_t)D_ * DH_);                                                    // 11
    hgemm_kernel<<<gMlp1, 256, HG_SMEM>>>(ao, w1, D_, DH_, b1, 1, nullptr, nullptr, hh);     // 12
    cvt_launch(W2, w2, (size_t)DH_ * D_);                                                    // 13
    hgemm_kernel<<<gProj, 256, HG_SMEM>>>(hh, w2, DH_, D_, b2, 0, x, y_, nullptr);           // 14
    ln_kernel<<<M_, 256>>>(y_, ln_g, ln_b, out);                                             // 15
}

// round 13
// speedup vs baseline: 1.0416x; 1.0416x over previous
#include <cuda_runtime.h>
#include <cuda_fp16.h>
#include <math.h>
#include <stdint.h>

#define B_    2
#define S_    4096
#define D_    2048
#define H_    16
#define DK_   128
#define DV_   128
#define SEG_  512
#define NSEG_ 8
#define DH_   8192
#define M_    (B_*S_)   // 8192 rows

// ---------------- scratch (device globals; no allocation allowed) ----------------
__device__ __align__(16) float g_y  [M_ * D_];
__device__ __align__(16) float g_U2 [512 * DK_ * DV_];
__device__ __align__(16) float g_zU2[512 * DK_];
__device__ __align__(16) float g_mem[B_*H_*NSEG_ * DK_ * DV_];
__device__ __align__(16) float g_z  [B_*H_*NSEG_ * DK_];
// fp16 tensors
__device__ __align__(16) __half g_x  [M_ * D_];
__device__ __align__(16) __half g_wq [D_ * D_];
__device__ __align__(16) __half g_wk [D_ * D_];
__device__ __align__(16) __half g_wv [D_ * D_];
__device__ __align__(16) __half g_wo [D_ * D_];
__device__ __align__(16) __half g_w1 [D_ * DH_];
__device__ __align__(16) __half g_w2 [DH_ * D_];
__device__ __align__(16) __half g_q  [M_ * D_];
__device__ __align__(16) __half g_k  [M_ * D_];
__device__ __align__(16) __half g_v  [M_ * D_];
__device__ __align__(16) __half g_atd[M_ * D_];
__device__ __align__(16) __half g_at [M_ * D_];
__device__ __align__(16) __half g_ao [M_ * D_];
__device__ __align__(16) __half g_hh [(size_t)M_ * DH_];

__device__ __forceinline__ float elu1(float x) { return x > 0.f ? x + 1.f : __expf(x); }

__device__ __forceinline__ uint32_t packh2(float a, float b) {
    __half2 h = __floats2half2_rn(a, b);
    return *(uint32_t*)&h;
}

// ================= mma helpers ===================================================
__device__ __forceinline__ void cp16(void* dst, const void* src) {
    uint32_t d = (uint32_t)__cvta_generic_to_shared(dst);
    asm volatile("cp.async.cg.shared.global [%0], [%1], 16;" :: "r"(d), "l"(src));
}

#define LDSM4(f, p) do { \
    uint32_t a_ = (uint32_t)__cvta_generic_to_shared(p); \
    asm volatile("ldmatrix.sync.aligned.m8n8.x4.shared.b16 {%0,%1,%2,%3}, [%4];" \
        : "=r"(f[0]), "=r"(f[1]), "=r"(f[2]), "=r"(f[3]) : "r"(a_)); \
} while (0)

#define LDSM4T(f, p) do { \
    uint32_t a_ = (uint32_t)__cvta_generic_to_shared(p); \
    asm volatile("ldmatrix.sync.aligned.m8n8.x4.trans.shared.b16 {%0,%1,%2,%3}, [%4];" \
        : "=r"(f[0]), "=r"(f[1]), "=r"(f[2]), "=r"(f[3]) : "r"(a_)); \
} while (0)

#define MMAH(d, a, b0, b1) \
    asm volatile("mma.sync.aligned.m16n8k16.row.col.f32.f16.f16.f32 " \
        "{%0,%1,%2,%3}, {%4,%5,%6,%7}, {%8,%9}, {%0,%1,%2,%3};" \
        : "+f"(d[0]), "+f"(d[1]), "+f"(d[2]), "+f"(d[3]) \
        : "r"(a[0]), "r"(a[1]), "r"(a[2]), "r"(a[3]), "r"(b0), "r"(b1))

// ================= fp16 tensor-core GEMM, CTA 128x128, warp 32x64, BK=64 =========
#define SA_STRIDE 72                 // 64 + 8 pad (half elems)
#define SB_STRIDE 136                // 128 + 8 pad
#define SA_STAGE  (128*SA_STRIDE)    // 9216
#define SB_STAGE  (64*SB_STRIDE)     // 8704
#define HG_SMEM ((SA_STAGE + SB_STAGE) * 2 * 2)   // 71680 bytes

__device__ __forceinline__ void hg_load_stage(
    const __half* __restrict__ Ag, const __half* __restrict__ Bg,
    __half* sA, __half* sB, int tid, size_t m0, size_t n0, int Kk, int Nn, int k0)
{
    // A: 128 rows x 64 cols = 1024 16B-chunks (4/thread)
#pragma unroll
    for (int it = 0; it < 4; it++) {
        int c = it*256 + tid;
        int r = c >> 3, col = (c & 7) << 3;
        cp16(sA + r * SA_STRIDE + col, Ag + (m0 + r) * (size_t)Kk + k0 + col);
    }
    // B: 64 rows x 128 cols = 1024 chunks (4/thread)
#pragma unroll
    for (int it = 0; it < 4; it++) {
        int c = it*256 + tid;
        int r = c >> 4, col = (c & 15) << 3;
        cp16(sB + r * SB_STRIDE + col, Bg + (size_t)(k0 + r) * Nn + n0 + col);
    }
    asm volatile("cp.async.commit_group;");
}

__global__ void __launch_bounds__(256)
hgemm_kernel(const __half* __restrict__ Ag, const __half* __restrict__ Bg,
             int Kk, int Nn,
             const float* __restrict__ bias, int relu, const float* __restrict__ resid,
             float* __restrict__ C, __half* __restrict__ Ch)
{
    extern __shared__ __half smem[];
    __half* sA = smem;
    __half* sB = smem + 2*SA_STAGE;

    int tid = threadIdx.x;
    int warp = tid >> 5, lane = tid & 31;
    int wm = warp >> 1, wn = warp & 1;
    size_t m0 = (size_t)blockIdx.y * 128;
    size_t n0 = (size_t)blockIdx.x * 128;

    float acc[2][8][4];
#pragma unroll
    for (int i = 0; i < 2; i++)
#pragma unroll
        for (int j = 0; j < 8; j++)
#pragma unroll
            for (int t = 0; t < 4; t++) acc[i][j][t] = 0.f;

    int nk = Kk >> 6;
    hg_load_stage(Ag, Bg, sA, sB, tid, m0, n0, Kk, Nn, 0);

    for (int kt = 0; kt < nk; kt++) {
        int cur = kt & 1;
        if (kt + 1 < nk) {
            hg_load_stage(Ag, Bg, sA + ((kt+1)&1)*SA_STAGE, sB + ((kt+1)&1)*SB_STAGE,
                          tid, m0, n0, Kk, Nn, (kt+1)*64);
            asm volatile("cp.async.wait_group 1;");
        } else {
            asm volatile("cp.async.wait_group 0;");
        }
        __syncthreads();

        __half* a = sA + cur*SA_STAGE;
        __half* bb = sB + cur*SB_STAGE;

#pragma unroll
        for (int k16 = 0; k16 < 64; k16 += 16) {
            uint32_t af[2][4], bf[4][4];
#pragma unroll
            for (int mi = 0; mi < 2; mi++)
                LDSM4(af[mi], a + (size_t)(wm*32 + mi*16 + (lane & 15)) * SA_STRIDE
                                + k16 + (lane >> 4) * 8);
#pragma unroll
            for (int nb = 0; nb < 4; nb++)
                LDSM4T(bf[nb], bb + (size_t)(k16 + (lane & 15)) * SB_STRIDE
                                  + wn*64 + nb*16 + (lane >> 4) * 8);
#pragma unroll
            for (int mi = 0; mi < 2; mi++)
#pragma unroll
                for (int ni = 0; ni < 8; ni++) {
                    int nb = ni >> 1, sel = (ni & 1) * 2;
                    MMAH(acc[mi][ni], af[mi], bf[nb][sel], bf[nb][sel+1]);
                }
        }
        __syncthreads();
    }

#pragma unroll
    for (int mi = 0; mi < 2; mi++)
#pragma unroll
        for (int ni = 0; ni < 8; ni++) {
            int col = wn*64 + ni*8 + (lane & 3) * 2;
#pragma unroll
            for (int hh = 0; hh < 2; hh++) {
                int row = wm*32 + mi*16 + (lane >> 2) + hh*8;
                float v0 = acc[mi][ni][hh*2], v1 = acc[mi][ni][hh*2+1];
                size_t o = (m0 + row) * (size_t)Nn + n0 + col;
                if (bias) { v0 += bias[n0+col]; v1 += bias[n0+col+1]; }
                if (resid) { v0 += resid[o]; v1 += resid[o+1]; }
                if (relu) { v0 = fmaxf(v0, 0.f); v1 = fmaxf(v1, 0.f); }
                if (C) { C[o] = v0; C[o+1] = v1; }
                if (Ch) *(uint32_t*)(Ch + o) = packh2(v0, v1);
            }
        }
}

// ---------------- fp32 -> fp16 converts ----------------------------------------
__global__ void __launch_bounds__(256)
cvt_kernel(const float4* __restrict__ in, __half2* __restrict__ out, int nquads)
{
    int i = blockIdx.x * 256 + threadIdx.x;
    if (i >= nquads) return;
    float4 v = in[i];
    out[2*i]   = __floats2half2_rn(v.x, v.y);
    out[2*i+1] = __floats2half2_rn(v.z, v.w);
}

__global__ void __launch_bounds__(256)
cvt3_kernel(const float4* __restrict__ a, const float4* __restrict__ b,
            const float4* __restrict__ c,
            __half2* __restrict__ oa, __half2* __restrict__ ob,
            __half2* __restrict__ oc, int nquads)
{
    int i = blockIdx.x * 256 + threadIdx.x;
    if (i >= nquads) return;
    const float4* in = (blockIdx.y == 0) ? a : (blockIdx.y == 1 ? b : c);
    __half2* out     = (blockIdx.y == 0) ? oa : (blockIdx.y == 1 ? ob : oc);
    float4 v = in[i];
    out[2*i]   = __floats2half2_rn(v.x, v.y);
    out[2*i+1] = __floats2half2_rn(v.z, v.w);
}

// ================= flash attention (fp16 mma, simple 3-tile form) ================
#define AT_STR 136
#define AT_TILE (64*AT_STR)
#define ATTN_SMEM_BYTES (3 * AT_TILE * 2)

__global__ void __launch_bounds__(128)
attn_mma_kernel(const __half* __restrict__ q, const __half* __restrict__ k,
                const __half* __restrict__ v, __half* __restrict__ atd)
{
    extern __shared__ __half sm[];
    __half* Qs = sm;
    __half* Ks = sm + AT_TILE;
    __half* Vs = sm + 2*AT_TILE;

    int qt = blockIdx.x, seg = blockIdx.y, bh = blockIdx.z;
    int b = bh >> 4, h = bh & 15;
    int tid = threadIdx.x, warp = tid >> 5, lane = tid & 31;
    const float scale = 0.08838834764831845f;
    size_t base = ((size_t)(b*S_ + seg*SEG_) * H_ + h) * DK_;

#pragma unroll
    for (int it = 0; it < 8; it++) {
        int e = it*128 + tid, r = e >> 4, c8 = (e & 15) << 3;
        size_t go = base + (size_t)(qt*64 + r)*2048 + c8;
        *(uint4*)(Qs + r*AT_STR + c8) = *(const uint4*)(q + go);
    }

    float o[16][4];
#pragma unroll
    for (int t = 0; t < 16; t++)
#pragma unroll
        for (int j = 0; j < 4; j++) o[t][j] = 0.f;
    float m0 = -1e30f, m1 = -1e30f, l0 = 0.f, l1 = 0.f;
    int r0g = qt*64 + warp*16 + (lane >> 2);
    int r1g = r0g + 8;

    for (int kt = 0; kt <= qt; kt++) {
        __syncthreads();
#pragma unroll
        for (int it = 0; it < 8; it++) {
            int e = it*128 + tid, r = e >> 4, c8 = (e & 15) << 3;
            size_t go = base + (size_t)(kt*64 + r)*2048 + c8;
            *(uint4*)(Ks + r*AT_STR + c8) = *(const uint4*)(k + go);
            *(uint4*)(Vs + r*AT_STR + c8) = *(const uint4*)(v + go);
        }
        __syncthreads();

        float s[8][4];
#pragma unroll
        for (int t = 0; t < 8; t++)
#pragma unroll
            for (int j = 0; j < 4; j++) s[t][j] = 0.f;

#pragma unroll
        for (int kk = 0; kk < 8; kk++) {
            uint32_t qa[4];
            LDSM4(qa, Qs + (size_t)(warp*16 + (lane & 15))*AT_STR + kk*16 + (lane >> 4)*8);
#pragma unroll
            for (int ng = 0; ng < 4; ng++) {
                uint32_t kf[4];
                LDSM4(kf, Ks + (size_t)(ng*16 + (lane & 15))*AT_STR + kk*16 + (lane >> 4)*8);
                MMAH(s[2*ng],   qa, kf[0], kf[2]);
                MMAH(s[2*ng+1], qa, kf[1], kf[3]);
            }
        }

        float mx0 = -1e30f, mx1 = -1e30f;
#pragma unroll
        for (int t = 0; t < 8; t++) {
            int colb = kt*64 + t*8 + (lane & 3)*2;
            float a0 = s[t][0]*scale, a1 = s[t][1]*scale;
            float a2 = s[t][2]*scale, a3 = s[t][3]*scale;
            if (kt == qt) {
                if (colb     > r0g) a0 = -1e30f;
                if (colb + 1 > r0g) a1 = -1e30f;
                if (colb     > r1g) a2 = -1e30f;
                if (colb + 1 > r1g) a3 = -1e30f;
            }
            s[t][0] = a0; s[t][1] = a1; s[t][2] = a2; s[t][3] = a3;
            mx0 = fmaxf(mx0, fmaxf(a0, a1));
            mx1 = fmaxf(mx1, fmaxf(a2, a3));
        }
        mx0 = fmaxf(mx0, __shfl_xor_sync(0xffffffffu, mx0, 1));
        mx0 = fmaxf(mx0, __shfl_xor_sync(0xffffffffu, mx0, 2));
        mx1 = fmaxf(mx1, __shfl_xor_sync(0xffffffffu, mx1, 1));
        mx1 = fmaxf(mx1, __shfl_xor_sync(0xffffffffu, mx1, 2));
        float m0n = fmaxf(m0, mx0), m1n = fmaxf(m1, mx1);
        float rc0 = __expf(m0 - m0n), rc1 = __expf(m1 - m1n);
        float sum0 = 0.f, sum1 = 0.f;
#pragma unroll
        for (int t = 0; t < 8; t++) {
            s[t][0] = __expf(s[t][0] - m0n); sum0 += s[t][0];
            s[t][1] = __expf(s[t][1] - m0n); sum0 += s[t][1];
            s[t][2] = __expf(s[t][2] - m1n); sum1 += s[t][2];
            s[t][3] = __expf(s[t][3] - m1n); sum1 += s[t][3];
        }
        sum0 += __shfl_xor_sync(0xffffffffu, sum0, 1);
        sum0 += __shfl_xor_sync(0xffffffffu, sum0, 2);
        sum1 += __shfl_xor_sync(0xffffffffu, sum1, 1);
        sum1 += __shfl_xor_sync(0xffffffffu, sum1, 2);
        l0 = l0*rc0 + sum0;  l1 = l1*rc1 + sum1;
        m0 = m0n;  m1 = m1n;
#pragma unroll
        for (int t = 0; t < 16; t++) {
            o[t][0] *= rc0; o[t][1] *= rc0; o[t][2] *= rc1; o[t][3] *= rc1;
        }

#pragma unroll
        for (int kk = 0; kk < 4; kk++) {
            uint32_t ah[4];
            ah[0] = packh2(s[2*kk][0],   s[2*kk][1]);
            ah[1] = packh2(s[2*kk][2],   s[2*kk][3]);
            ah[2] = packh2(s[2*kk+1][0], s[2*kk+1][1]);
            ah[3] = packh2(s[2*kk+1][2], s[2*kk+1][3]);
#pragma unroll
            for (int dg = 0; dg < 8; dg++) {
                uint32_t vf[4];
                LDSM4T(vf, Vs + (size_t)(kk*16 + (lane & 15))*AT_STR + dg*16 + (lane >> 4)*8);
                MMAH(o[2*dg],   ah, vf[0], vf[1]);
                MMAH(o[2*dg+1], ah, vf[2], vf[3]);
            }
        }
    }

    float inv0 = 1.f / l0, inv1 = 1.f / l1;
#pragma unroll
    for (int t = 0; t < 16; t++) {
        size_t ro = base + (size_t)(qt*64 + warp*16 + (lane >> 2))*2048 + t*8 + (lane & 3)*2;
        *(uint32_t*)(atd + ro)          = packh2(o[t][0]*inv0, o[t][1]*inv0);
        *(uint32_t*)(atd + ro + 8*2048) = packh2(o[t][2]*inv1, o[t][3]*inv1);
    }
}

// ================= memory update: U = sig(K)^T V over HALF segments ==============
#define MU_KSTR 72
#define MU_KTILE (128*MU_KSTR)
#define MU_VSTR 136
#define MU_VTILE (64*MU_VSTR)
#define MEMUPD_SMEM ((MU_KTILE + MU_VTILE) * 2)

__global__ void __launch_bounds__(256)
memupd_mma_kernel(const __half* __restrict__ k, const __half* __restrict__ v,
                  float* __restrict__ U2, float* __restrict__ zU2)
{
    extern __shared__ __half sm[];
    __half* sK = sm;
    __half* sV = sm + MU_KTILE;
    __shared__ float zsm[128];

    int hseg = blockIdx.x & 15, bhx = blockIdx.x >> 4;
    int b = bhx >> 4, h = bhx & 15;
    int tid = threadIdx.x, warp = tid >> 5, lane = tid & 31;
    int wm = warp >> 1, wn = warp & 1;
    size_t base = ((size_t)(b*S_ + hseg*256) * H_ + h) * DK_;

    if (tid < 128) zsm[tid] = 0.f;

    float acc[2][8][4];
#pragma unroll
    for (int i = 0; i < 2; i++)
#pragma unroll
        for (int j = 0; j < 8; j++)
#pragma unroll
            for (int t = 0; t < 4; t++) acc[i][j][t] = 0.f;

    for (int st = 0; st < 4; st++) {
        int s0 = st * 64;
#pragma unroll
        for (int it = 0; it < 16; it++) {
            int e = it*256 + tid, s = e >> 6, c2 = e & 63;
            size_t go = base + (size_t)(s0 + s)*2048 + 2*c2;
            __half2 h2 = *(const __half2*)(k + go);
            sK[(2*c2)  *MU_KSTR + s] = __float2half_rn(elu1(__low2float(h2)));
            sK[(2*c2+1)*MU_KSTR + s] = __float2half_rn(elu1(__high2float(h2)));
        }
#pragma unroll
        for (int it = 0; it < 4; it++) {
            int e = it*256 + tid, r = e >> 4, c8 = (e & 15) << 3;
            size_t go = base + (size_t)(s0 + r)*2048 + c8;
            *(uint4*)(sV + r*MU_VSTR + c8) = *(const uint4*)(v + go);
        }
        __syncthreads();

        if (tid < 128) {
            float zz = 0.f;
#pragma unroll 4
            for (int s = 0; s < 64; s++) zz += __half2float(sK[tid*MU_KSTR + s]);
            zsm[tid] += zz;
        }

#pragma unroll
        for (int kk = 0; kk < 4; kk++) {
            uint32_t a[2][4];
#pragma unroll
            for (int mi = 0; mi < 2; mi++)
                LDSM4(a[mi], sK + (size_t)(wm*32 + mi*16 + (lane & 15))*MU_KSTR + kk*16 + (lane >> 4)*8);
#pragma unroll
            for (int ng = 0; ng < 4; ng++) {
                uint32_t bb[4];
                LDSM4T(bb, sV + (size_t)(kk*16 + (lane & 15))*MU_VSTR + wn*64 + ng*16 + (lane >> 4)*8);
#pragma unroll
                for (int mi = 0; mi < 2; mi++) {
                    MMAH(acc[mi][2*ng],   a[mi], bb[0], bb[1]);
                    MMAH(acc[mi][2*ng+1], a[mi], bb[2], bb[3]);
                }
            }
        }
        __syncthreads();
    }

    size_t ob = (size_t)blockIdx.x * (DK_*DV_);
#pragma unroll
    for (int mi = 0; mi < 2; mi++)
#pragma unroll
        for (int ni = 0; ni < 8; ni++) {
            int col = wn*64 + ni*8 + (lane & 3)*2;
#pragma unroll
            for (int hh = 0; hh < 2; hh++) {
                int row = wm*32 + mi*16 + (lane >> 2) + hh*8;
                float2 w; w.x = acc[mi][ni][hh*2]; w.y = acc[mi][ni][hh*2+1];
                *(float2*)(U2 + ob + (size_t)row*128 + col) = w;
            }
        }
    if (tid < 128) zU2[(size_t)blockIdx.x*128 + tid] = zsm[tid];
}

// ---------------- exclusive prefix over segments --------------------------------
__global__ void __launch_bounds__(256)
prefix_kernel(const float* __restrict__ U2, const float* __restrict__ zU2,
              float* __restrict__ Mem, float* __restrict__ Z)
{
    int bh = blockIdx.x, tid = threadIdx.x;
    for (int idx = tid; idx < DK_*DV_; idx += 256) {
        float run = 0.f;
#pragma unroll
        for (int sg = 0; sg < NSEG_; sg++) {
            Mem[((size_t)(bh*NSEG_ + sg)) * (DK_*DV_) + idx] = run;
            run += U2[((size_t)(bh*16 + 2*sg))   * (DK_*DV_) + idx]
                 + U2[((size_t)(bh*16 + 2*sg+1)) * (DK_*DV_) + idx];
        }
    }
    if (tid < 128) {
        float run = 1.f / 128.f;
#pragma unroll
        for (int sg = 0; sg < NSEG_; sg++) {
            Z[(size_t)(bh*NSEG_ + sg) * 128 + tid] = run;
            run += zU2[(size_t)(bh*16 + 2*sg)   * 128 + tid]
                 + zU2[(size_t)(bh*16 + 2*sg+1) * 128 + tid];
        }
    }
}

// ================= retrieval + gate combine (fp16 mma) ===========================
#define RT_STR 136
#define RT_TILE (128*RT_STR)
#define RETR_SMEM (2 * RT_TILE * 2)

__global__ void __launch_bounds__(256)
retrieve_mma_kernel(const __half* __restrict__ q, const float* __restrict__ Mem,
                    const float* __restrict__ Z, const float* __restrict__ betas,
                    const __half* __restrict__ atd, __half* __restrict__ at)
{
    extern __shared__ __half sm[];
    __half* Mh = sm;
    __half* Sh = sm + RT_TILE;
    __shared__ float den[128], zz[128], gate[128], denp[256];

    int seg = blockIdx.x & 7, bhx = blockIdx.x >> 3;
    int b = bhx >> 4, h = bhx & 15;
    int tid = threadIdx.x, warp = tid >> 5, lane = tid & 31;
    size_t base = ((size_t)(b*S_ + seg*SEG_) * H_ + h) * DK_;
    size_t mb = (size_t)blockIdx.x * 16384;

    if (tid < 128) {
        gate[tid] = 1.f / (1.f + __expf(-betas[h*128 + tid]));
        zz[tid]   = Z[(size_t)blockIdx.x*128 + tid];
    }
#pragma unroll
    for (int it = 0; it < 16; it++) {
        int e = it*256 + tid, r = e >> 5, c4 = (e & 31) << 2;
        float4 v = *(const float4*)(Mem + mb + (size_t)r*128 + c4);
        *(__half2*)(Mh + r*RT_STR + c4)     = __floats2half2_rn(v.x, v.y);
        *(__half2*)(Mh + r*RT_STR + c4 + 2) = __floats2half2_rn(v.z, v.w);
    }
    __syncthreads();

    for (int ch = 0; ch < 4; ch++) {
        int s0 = ch * 128;
#pragma unroll
        for (int it = 0; it < 32; it++) {
            int e = it*256 + tid, s = e >> 6, c2 = e & 63;
            size_t go = base + (size_t)(s0 + s)*2048 + 2*c2;
            __half2 h2 = *(const __half2*)(q + go);
            *(__half2*)(Sh + s*RT_STR + 2*c2) =
                __floats2half2_rn(elu1(__low2float(h2)), elu1(__high2float(h2)));
        }
        __syncthreads();
        {
            int r = tid >> 1, hf = tid & 1;
            float d = 0.f;
#pragma unroll 4
            for (int dk = hf*64; dk < hf*64 + 64; dk++)
                d += __half2float(Sh[r*RT_STR + dk]) * zz[dk];
            denp[tid] = d;
        }
        __syncthreads();
        if (tid < 128) den[tid] = denp[2*tid] + denp[2*tid+1];
        __syncthreads();

        float o[16][4];
#pragma unroll
        for (int t = 0; t < 16; t++)
#pragma unroll
            for (int j = 0; j < 4; j++) o[t][j] = 0.f;

#pragma unroll
        for (int kk = 0; kk < 8; kk++) {
            uint32_t qa[4];
            LDSM4(qa, Sh + (size_t)(warp*16 + (lane & 15))*RT_STR + kk*16 + (lane >> 4)*8);
#pragma unroll
            for (int ng = 0; ng < 8; ng++) {
                uint32_t mh4[4];
                LDSM4T(mh4, Mh + (size_t)(kk*16 + (lane & 15))*RT_STR + ng*16 + (lane >> 4)*8);
                MMAH(o[2*ng],   qa, mh4[0], mh4[1]);
                MMAH(o[2*ng+1], qa, mh4[2], mh4[3]);
            }
        }

        float inv0 = 1.f / den[warp*16 + (lane >> 2)];
        float inv1 = 1.f / den[warp*16 + (lane >> 2) + 8];
#pragma unroll
        for (int t = 0; t < 16; t++) {
            int col = t*8 + (lane & 3)*2;
            float g0 = gate[col], g1 = gate[col+1];
            size_t ro = base + (size_t)(s0 + warp*16 + (lane >> 2))*2048 + col;
            __half2 d0 = *(const __half2*)(atd + ro);
            __half2 d1 = *(const __half2*)(atd + ro + 8*2048);
            float v0 = g0*(o[t][0]*inv0) + (1.f - g0)*__low2float(d0);
            float v1 = g1*(o[t][1]*inv0) + (1.f - g1)*__high2float(d0);
            float v2 = g0*(o[t][2]*inv1) + (1.f - g0)*__low2float(d1);
            float v3 = g1*(o[t][3]*inv1) + (1.f - g1)*__high2float(d1);
            *(uint32_t*)(at + ro)          = packh2(v0, v1);
            *(uint32_t*)(at + ro + 8*2048) = packh2(v2, v3);
        }
        __syncthreads();
    }
}

// ---------------- LayerNorm -----------------------------------------------------
__global__ void __launch_bounds__(256)
ln_kernel(const float* __restrict__ y, const float* __restrict__ gg,
          const float* __restrict__ bb, float* __restrict__ out)
{
    size_t row = blockIdx.x;
    const float* p = y + row * D_;
    int tid = threadIdx.x;
    float4 v0 = *(const float4*)(p + tid*8);
    float4 v1 = *(const float4*)(p + tid*8 + 4);
    float s  = v0.x+v0.y+v0.z+v0.w + v1.x+v1.y+v1.z+v1.w;
    float s2 = v0.x*v0.x+v0.y*v0.y+v0.z*v0.z+v0.w*v0.w
             + v1.x*v1.x+v1.y*v1.y+v1.z*v1.z+v1.w*v1.w;
#pragma unroll
    for (int o = 16; o >= 1; o >>= 1) {
        s  += __shfl_xor_sync(0xffffffffu, s, o);
        s2 += __shfl_xor_sync(0xffffffffu, s2, o);
    }
    __shared__ float red[16];
    __shared__ float stat[2];
    int warp = tid >> 5, lane = tid & 31;
    if (lane == 0) { red[warp] = s; red[warp + 8] = s2; }
    __syncthreads();
    if (tid == 0) {
        float S = 0.f, S2 = 0.f;
#pragma unroll
        for (int w = 0; w < 8; w++) { S += red[w]; S2 += red[w + 8]; }
        float mean = S / (float)D_;
        float var  = S2 / (float)D_ - mean*mean;
        stat[0] = mean;
        stat[1] = rsqrtf(var + 1e-5f);
    }
    __syncthreads();
    float mean = stat[0], inv = stat[1];
    float4 g0 = *(const float4*)(gg + tid*8), g1 = *(const float4*)(gg + tid*8 + 4);
    float4 b0 = *(const float4*)(bb + tid*8), b1 = *(const float4*)(bb + tid*8 + 4);
    float4 o0, o1;
    o0.x = (v0.x-mean)*inv*g0.x + b0.x; o0.y = (v0.y-mean)*inv*g0.y + b0.y;
    o0.z = (v0.z-mean)*inv*g0.z + b0.z; o0.w = (v0.w-mean)*inv*g0.w + b0.w;
    o1.x = (v1.x-mean)*inv*g1.x + b1.x; o1.y = (v1.y-mean)*inv*g1.y + b1.y;
    o1.z = (v1.z-mean)*inv*g1.z + b1.z; o1.w = (v1.w-mean)*inv*g1.w + b1.w;
    *(float4*)(out + row*D_ + tid*8)     = o0;
    *(float4*)(out + row*D_ + tid*8 + 4) = o1;
}

// ---------------- launch --------------------------------------------------------
static inline void cvt_launch(const float* src, __half* dst, size_t nelems)
{
    int nq = (int)(nelems / 4);
    cvt_kernel<<<(nq + 255)/256, 256>>>((const float4*)src, (__half2*)dst, nq);
}

extern "C" void kernel_launch(void* const* d_in, const int* in_sizes, int n_in,
                              void* d_out, int out_size)
{
    const float* x     = (const float*)d_in[0];
    const float* Wq    = (const float*)d_in[1];
    const float* Wk    = (const float*)d_in[2];
    const float* Wv    = (const float*)d_in[3];
    const float* Wo    = (const float*)d_in[4];
    const float* betas = (const float*)d_in[5];
    const float* W1    = (const float*)d_in[6];
    const float* b1    = (const float*)d_in[7];
    const float* W2    = (const float*)d_in[8];
    const float* b2    = (const float*)d_in[9];
    const float* ln_g  = (const float*)d_in[10];
    const float* ln_b  = (const float*)d_in[11];
    float* out = (float*)d_out;

    float *y_, *U2_, *zU2_, *mem_, *z_;
    cudaGetSymbolAddress((void**)&y_,   g_y);
    cudaGetSymbolAddress((void**)&U2_,  g_U2);
    cudaGetSymbolAddress((void**)&zU2_, g_zU2);
    cudaGetSymbolAddress((void**)&mem_, g_mem);
    cudaGetSymbolAddress((void**)&z_,   g_z);

    __half *xh,*wq,*wk,*wv,*wo,*w1,*w2,*qh,*kh,*vh,*atd,*at,*ao,*hh;
    cudaGetSymbolAddress((void**)&xh,  g_x);
    cudaGetSymbolAddress((void**)&wq,  g_wq);
    cudaGetSymbolAddress((void**)&wk,  g_wk);
    cudaGetSymbolAddress((void**)&wv,  g_wv);
    cudaGetSymbolAddress((void**)&wo,  g_wo);
    cudaGetSymbolAddress((void**)&w1,  g_w1);
    cudaGetSymbolAddress((void**)&w2,  g_w2);
    cudaGetSymbolAddress((void**)&qh,  g_q);
    cudaGetSymbolAddress((void**)&kh,  g_k);
    cudaGetSymbolAddress((void**)&vh,  g_v);
    cudaGetSymbolAddress((void**)&atd, g_atd);
    cudaGetSymbolAddress((void**)&at,  g_at);
    cudaGetSymbolAddress((void**)&ao,  g_ao);
    cudaGetSymbolAddress((void**)&hh,  g_hh);

    cudaFuncSetAttribute(hgemm_kernel,
        cudaFuncAttributeMaxDynamicSharedMemorySize, HG_SMEM);
    cudaFuncSetAttribute(attn_mma_kernel,
        cudaFuncAttributeMaxDynamicSharedMemorySize, ATTN_SMEM_BYTES);
    cudaFuncSetAttribute(memupd_mma_kernel,
        cudaFuncAttributeMaxDynamicSharedMemorySize, MEMUPD_SMEM);
    cudaFuncSetAttribute(retrieve_mma_kernel,
        cudaFuncAttributeMaxDynamicSharedMemorySize, RETR_SMEM);

    dim3 gProj(D_/128, M_/128);          // (16, 64)
    dim3 gMlp1(DH_/128, M_/128);         // (64, 64)

    // idx 0..4: converts + QKV GEMMs; idx 5 = attn_mma (ncu -s 5 target)
    cvt_launch(x, xh, (size_t)M_ * D_);                                     // 0
    {
        int nq = (int)((size_t)D_ * D_ / 4);
        cvt3_kernel<<<dim3((nq + 255)/256, 3), 256>>>(                      // 1
            (const float4*)Wq, (const float4*)Wk, (const float4*)Wv,
            (__half2*)wq, (__half2*)wk, (__half2*)wv, nq);
    }
    hgemm_kernel<<<gProj, 256, HG_SMEM>>>(xh, wq, D_, D_, nullptr, 0, nullptr, nullptr, qh); // 2
    hgemm_kernel<<<gProj, 256, HG_SMEM>>>(xh, wk, D_, D_, nullptr, 0, nullptr, nullptr, kh); // 3
    hgemm_kernel<<<gProj, 256, HG_SMEM>>>(xh, wv, D_, D_, nullptr, 0, nullptr, nullptr, vh); // 4

    attn_mma_kernel<<<dim3(8, 8, 32), 128, ATTN_SMEM_BYTES>>>(qh, kh, vh, atd);              // 5
    memupd_mma_kernel<<<512, 256, MEMUPD_SMEM>>>(kh, vh, U2_, zU2_);                         // 6
    prefix_kernel<<<32, 256>>>(U2_, zU2_, mem_, z_);                                         // 7
    cvt_launch(Wo, wo, (size_t)D_ * D_);                                                     // 8
    retrieve_mma_kernel<<<256, 256, RETR_SMEM>>>(qh, mem_, z_, betas, atd, at);              // 9

    hgemm_kernel<<<gProj, 256, HG_SMEM>>>(at, wo, D_, D_, nullptr, 0, nullptr, nullptr, ao); // 10
    cvt_launch(W1, w1, (size_t)D_ * DH_);                                                    // 11
    hgemm_kernel<<<gMlp1, 256, HG_SMEM>>>(ao, w1, D_, DH_, b1, 1, nullptr, nullptr, hh);     // 12
    cvt_launch(W2, w2, (size_t)DH_ * D_);                                                    // 13
    hgemm_kernel<<<gProj, 256, HG_SMEM>>>(hh, w2, DH_, D_, b2, 0, x, y_, nullptr);           // 14
    ln_kernel<<<M_, 256>>>(y_, ln_g, ln_b, out);                                             // 15
}

// round 14
// speedup vs baseline: 1.0592x; 1.0170x over previous
#include <cuda_runtime.h>
#include <cuda_fp16.h>
#include <math.h>
#include <stdint.h>

#define B_    2
#define S_    4096
#define D_    2048
#define H_    16
#define DK_   128
#define DV_   128
#define SEG_  512
#define NSEG_ 8
#define DH_   8192
#define M_    (B_*S_)   // 8192 rows

// ---------------- scratch (device globals; no allocation allowed) ----------------
__device__ __align__(16) float g_y  [M_ * D_];
__device__ __align__(16) float g_U2 [512 * DK_ * DV_];
__device__ __align__(16) float g_zU2[512 * DK_];
__device__ __align__(16) float g_mem[B_*H_*NSEG_ * DK_ * DV_];
__device__ __align__(16) float g_z  [B_*H_*NSEG_ * DK_];
// fp16 tensors
__device__ __align__(16) __half g_x  [M_ * D_];
__device__ __align__(16) __half g_wq [D_ * D_];
__device__ __align__(16) __half g_wk [D_ * D_];
__device__ __align__(16) __half g_wv [D_ * D_];
__device__ __align__(16) __half g_wo [D_ * D_];
__device__ __align__(16) __half g_w1 [D_ * DH_];
__device__ __align__(16) __half g_w2 [DH_ * D_];
__device__ __align__(16) __half g_q  [M_ * D_];
__device__ __align__(16) __half g_k  [M_ * D_];
__device__ __align__(16) __half g_v  [M_ * D_];
__device__ __align__(16) __half g_atd[M_ * D_];
__device__ __align__(16) __half g_at [M_ * D_];
__device__ __align__(16) __half g_ao [M_ * D_];
__device__ __align__(16) __half g_hh [(size_t)M_ * DH_];

__device__ __forceinline__ float elu1(float x) { return x > 0.f ? x + 1.f : __expf(x); }

__device__ __forceinline__ uint32_t packh2(float a, float b) {
    __half2 h = __floats2half2_rn(a, b);
    return *(uint32_t*)&h;
}

// ================= mma helpers ===================================================
__device__ __forceinline__ void cp16(void* dst, const void* src) {
    uint32_t d = (uint32_t)__cvta_generic_to_shared(dst);
    asm volatile("cp.async.cg.shared.global [%0], [%1], 16;" :: "r"(d), "l"(src));
}

#define LDSM4(f, p) do { \
    uint32_t a_ = (uint32_t)__cvta_generic_to_shared(p); \
    asm volatile("ldmatrix.sync.aligned.m8n8.x4.shared.b16 {%0,%1,%2,%3}, [%4];" \
        : "=r"(f[0]), "=r"(f[1]), "=r"(f[2]), "=r"(f[3]) : "r"(a_)); \
} while (0)

#define LDSM4T(f, p) do { \
    uint32_t a_ = (uint32_t)__cvta_generic_to_shared(p); \
    asm volatile("ldmatrix.sync.aligned.m8n8.x4.trans.shared.b16 {%0,%1,%2,%3}, [%4];" \
        : "=r"(f[0]), "=r"(f[1]), "=r"(f[2]), "=r"(f[3]) : "r"(a_)); \
} while (0)

#define MMAH(d, a, b0, b1) \
    asm volatile("mma.sync.aligned.m16n8k16.row.col.f32.f16.f16.f32 " \
        "{%0,%1,%2,%3}, {%4,%5,%6,%7}, {%8,%9}, {%0,%1,%2,%3};" \
        : "+f"(d[0]), "+f"(d[1]), "+f"(d[2]), "+f"(d[3]) \
        : "r"(a[0]), "r"(a[1]), "r"(a[2]), "r"(a[3]), "r"(b0), "r"(b1))

// ================= fp16 tensor-core GEMM, CTA 128x128, warp 32x64, BK=64 =========
#define SA_STRIDE 72
#define SB_STRIDE 136
#define SA_STAGE  (128*SA_STRIDE)
#define SB_STAGE  (64*SB_STRIDE)
#define HG_SMEM ((SA_STAGE + SB_STAGE) * 2 * 2)   // 71680 bytes

__device__ __forceinline__ void hg_load_stage(
    const __half* __restrict__ Ag, const __half* __restrict__ Bg,
    __half* sA, __half* sB, int tid, size_t m0, size_t n0, int Kk, int Nn, int k0)
{
#pragma unroll
    for (int it = 0; it < 4; it++) {
        int c = it*256 + tid;
        int r = c >> 3, col = (c & 7) << 3;
        cp16(sA + r * SA_STRIDE + col, Ag + (m0 + r) * (size_t)Kk + k0 + col);
    }
#pragma unroll
    for (int it = 0; it < 4; it++) {
        int c = it*256 + tid;
        int r = c >> 4, col = (c & 15) << 3;
        cp16(sB + r * SB_STRIDE + col, Bg + (size_t)(k0 + r) * Nn + n0 + col);
    }
    asm volatile("cp.async.commit_group;");
}

__device__ __forceinline__ void hgemm_body(
    const __half* __restrict__ Ag, const __half* __restrict__ Bg,
    int Kk, int Nn,
    const float* __restrict__ bias, int relu, const float* __restrict__ resid,
    float* __restrict__ C, __half* __restrict__ Ch,
    __half* smem, size_t m0, size_t n0)
{
    __half* sA = smem;
    __half* sB = smem + 2*SA_STAGE;

    int tid = threadIdx.x;
    int warp = tid >> 5, lane = tid & 31;
    int wm = warp >> 1, wn = warp & 1;

    float acc[2][8][4];
#pragma unroll
    for (int i = 0; i < 2; i++)
#pragma unroll
        for (int j = 0; j < 8; j++)
#pragma unroll
            for (int t = 0; t < 4; t++) acc[i][j][t] = 0.f;

    int nk = Kk >> 6;
    hg_load_stage(Ag, Bg, sA, sB, tid, m0, n0, Kk, Nn, 0);

    for (int kt = 0; kt < nk; kt++) {
        int cur = kt & 1;
        if (kt + 1 < nk) {
            hg_load_stage(Ag, Bg, sA + ((kt+1)&1)*SA_STAGE, sB + ((kt+1)&1)*SB_STAGE,
                          tid, m0, n0, Kk, Nn, (kt+1)*64);
            asm volatile("cp.async.wait_group 1;");
        } else {
            asm volatile("cp.async.wait_group 0;");
        }
        __syncthreads();

        __half* a = sA + cur*SA_STAGE;
        __half* bb = sB + cur*SB_STAGE;

#pragma unroll
        for (int k16 = 0; k16 < 64; k16 += 16) {
            uint32_t af[2][4];
#pragma unroll
            for (int mi = 0; mi < 2; mi++)
                LDSM4(af[mi], a + (size_t)(wm*32 + mi*16 + (lane & 15)) * SA_STRIDE
                                + k16 + (lane >> 4) * 8);
            // per-nb interleave: load B tile then immediately use it
#pragma unroll
            for (int nb = 0; nb < 4; nb++) {
                uint32_t bf[4];
                LDSM4T(bf, bb + (size_t)(k16 + (lane & 15)) * SB_STRIDE
                              + wn*64 + nb*16 + (lane >> 4) * 8);
                MMAH(acc[0][2*nb],   af[0], bf[0], bf[1]);
                MMAH(acc[1][2*nb],   af[1], bf[0], bf[1]);
                MMAH(acc[0][2*nb+1], af[0], bf[2], bf[3]);
                MMAH(acc[1][2*nb+1], af[1], bf[2], bf[3]);
            }
        }
        __syncthreads();
    }

#pragma unroll
    for (int mi = 0; mi < 2; mi++)
#pragma unroll
        for (int ni = 0; ni < 8; ni++) {
            int col = wn*64 + ni*8 + (lane & 3) * 2;
#pragma unroll
            for (int hh = 0; hh < 2; hh++) {
                int row = wm*32 + mi*16 + (lane >> 2) + hh*8;
                float v0 = acc[mi][ni][hh*2], v1 = acc[mi][ni][hh*2+1];
                size_t o = (m0 + row) * (size_t)Nn + n0 + col;
                if (bias) { v0 += bias[n0+col]; v1 += bias[n0+col+1]; }
                if (resid) { v0 += resid[o]; v1 += resid[o+1]; }
                if (relu) { v0 = fmaxf(v0, 0.f); v1 = fmaxf(v1, 0.f); }
                if (C) { C[o] = v0; C[o+1] = v1; }
                if (Ch) *(uint32_t*)(Ch + o) = packh2(v0, v1);
            }
        }
}

__global__ void __launch_bounds__(256)
hgemm_kernel(const __half* __restrict__ Ag, const __half* __restrict__ Bg,
             int Kk, int Nn,
             const float* __restrict__ bias, int relu, const float* __restrict__ resid,
             float* __restrict__ C, __half* __restrict__ Ch)
{
    extern __shared__ __half smem[];
    hgemm_body(Ag, Bg, Kk, Nn, bias, relu, resid, C, Ch, smem,
               (size_t)blockIdx.y * 128, (size_t)blockIdx.x * 128);
}

// merged QKV: grid.z selects weight/output
__global__ void __launch_bounds__(256)
hgemm_qkv_kernel(const __half* __restrict__ Ag,
                 const __half* __restrict__ W0, const __half* __restrict__ W1g,
                 const __half* __restrict__ W2g,
                 __half* __restrict__ O0, __half* __restrict__ O1,
                 __half* __restrict__ O2)
{
    extern __shared__ __half smem[];
    const __half* Bg = (blockIdx.z == 0) ? W0 : (blockIdx.z == 1 ? W1g : W2g);
    __half* Ch       = (blockIdx.z == 0) ? O0 : (blockIdx.z == 1 ? O1 : O2);
    hgemm_body(Ag, Bg, D_, D_, nullptr, 0, nullptr, nullptr, Ch, smem,
               (size_t)blockIdx.y * 128, (size_t)blockIdx.x * 128);
}

// ---------------- fp32 -> fp16 converts ----------------------------------------
__global__ void __launch_bounds__(256)
cvt_kernel(const float4* __restrict__ in, __half2* __restrict__ out, int nquads)
{
    int i = blockIdx.x * 256 + threadIdx.x;
    if (i >= nquads) return;
    float4 v = in[i];
    out[2*i]   = __floats2half2_rn(v.x, v.y);
    out[2*i+1] = __floats2half2_rn(v.z, v.w);
}

__global__ void __launch_bounds__(256)
cvt3_kernel(const float4* __restrict__ a, const float4* __restrict__ b,
            const float4* __restrict__ c,
            __half2* __restrict__ oa, __half2* __restrict__ ob,
            __half2* __restrict__ oc,
            int na, int nb, int nc)
{
    int i = blockIdx.x * 256 + threadIdx.x;
    const float4* in; __half2* out; int n;
    if (blockIdx.y == 0)      { in = a; out = oa; n = na; }
    else if (blockIdx.y == 1) { in = b; out = ob; n = nb; }
    else                      { in = c; out = oc; n = nc; }
    if (i >= n) return;
    float4 v = in[i];
    out[2*i]   = __floats2half2_rn(v.x, v.y);
    out[2*i+1] = __floats2half2_rn(v.z, v.w);
}

// ================= flash attention (fp16 mma, simple 3-tile form) ================
#define AT_STR 136
#define AT_TILE (64*AT_STR)
#define ATTN_SMEM_BYTES (3 * AT_TILE * 2)

__global__ void __launch_bounds__(128)
attn_mma_kernel(const __half* __restrict__ q, const __half* __restrict__ k,
                const __half* __restrict__ v, __half* __restrict__ atd)
{
    extern __shared__ __half sm[];
    __half* Qs = sm;
    __half* Ks = sm + AT_TILE;
    __half* Vs = sm + 2*AT_TILE;

    int qt = blockIdx.x, seg = blockIdx.y, bh = blockIdx.z;
    int b = bh >> 4, h = bh & 15;
    int tid = threadIdx.x, warp = tid >> 5, lane = tid & 31;
    const float scale = 0.08838834764831845f;
    size_t base = ((size_t)(b*S_ + seg*SEG_) * H_ + h) * DK_;

#pragma unroll
    for (int it = 0; it < 8; it++) {
        int e = it*128 + tid, r = e >> 4, c8 = (e & 15) << 3;
        size_t go = base + (size_t)(qt*64 + r)*2048 + c8;
        *(uint4*)(Qs + r*AT_STR + c8) = *(const uint4*)(q + go);
    }

    float o[16][4];
#pragma unroll
    for (int t = 0; t < 16; t++)
#pragma unroll
        for (int j = 0; j < 4; j++) o[t][j] = 0.f;
    float m0 = -1e30f, m1 = -1e30f, l0 = 0.f, l1 = 0.f;
    int r0g = qt*64 + warp*16 + (lane >> 2);
    int r1g = r0g + 8;

    for (int kt = 0; kt <= qt; kt++) {
        __syncthreads();
#pragma unroll
        for (int it = 0; it < 8; it++) {
            int e = it*128 + tid, r = e >> 4, c8 = (e & 15) << 3;
            size_t go = base + (size_t)(kt*64 + r)*2048 + c8;
            *(uint4*)(Ks + r*AT_STR + c8) = *(const uint4*)(k + go);
            *(uint4*)(Vs + r*AT_STR + c8) = *(const uint4*)(v + go);
        }
        __syncthreads();

        float s[8][4];
#pragma unroll
        for (int t = 0; t < 8; t++)
#pragma unroll
            for (int j = 0; j < 4; j++) s[t][j] = 0.f;

#pragma unroll
        for (int kk = 0; kk < 8; kk++) {
            uint32_t qa[4];
            LDSM4(qa, Qs + (size_t)(warp*16 + (lane & 15))*AT_STR + kk*16 + (lane >> 4)*8);
#pragma unroll
            for (int ng = 0; ng < 4; ng++) {
                uint32_t kf[4];
                LDSM4(kf, Ks + (size_t)(ng*16 + (lane & 15))*AT_STR + kk*16 + (lane >> 4)*8);
                MMAH(s[2*ng],   qa, kf[0], kf[2]);
                MMAH(s[2*ng+1], qa, kf[1], kf[3]);
            }
        }

        float mx0 = -1e30f, mx1 = -1e30f;
#pragma unroll
        for (int t = 0; t < 8; t++) {
            int colb = kt*64 + t*8 + (lane & 3)*2;
            float a0 = s[t][0]*scale, a1 = s[t][1]*scale;
            float a2 = s[t][2]*scale, a3 = s[t][3]*scale;
            if (kt == qt) {
                if (colb     > r0g) a0 = -1e30f;
                if (colb + 1 > r0g) a1 = -1e30f;
                if (colb     > r1g) a2 = -1e30f;
                if (colb + 1 > r1g) a3 = -1e30f;
            }
            s[t][0] = a0; s[t][1] = a1; s[t][2] = a2; s[t][3] = a3;
            mx0 = fmaxf(mx0, fmaxf(a0, a1));
            mx1 = fmaxf(mx1, fmaxf(a2, a3));
        }
        mx0 = fmaxf(mx0, __shfl_xor_sync(0xffffffffu, mx0, 1));
        mx0 = fmaxf(mx0, __shfl_xor_sync(0xffffffffu, mx0, 2));
        mx1 = fmaxf(mx1, __shfl_xor_sync(0xffffffffu, mx1, 1));
        mx1 = fmaxf(mx1, __shfl_xor_sync(0xffffffffu, mx1, 2));
        float m0n = fmaxf(m0, mx0), m1n = fmaxf(m1, mx1);
        float rc0 = __expf(m0 - m0n), rc1 = __expf(m1 - m1n);
        float sum0 = 0.f, sum1 = 0.f;
#pragma unroll
        for (int t = 0; t < 8; t++) {
            s[t][0] = __expf(s[t][0] - m0n); sum0 += s[t][0];
            s[t][1] = __expf(s[t][1] - m0n); sum0 += s[t][1];
            s[t][2] = __expf(s[t][2] - m1n); sum1 += s[t][2];
            s[t][3] = __expf(s[t][3] - m1n); sum1 += s[t][3];
        }
        sum0 += __shfl_xor_sync(0xffffffffu, sum0, 1);
        sum0 += __shfl_xor_sync(0xffffffffu, sum0, 2);
        sum1 += __shfl_xor_sync(0xffffffffu, sum1, 1);
        sum1 += __shfl_xor_sync(0xffffffffu, sum1, 2);
        l0 = l0*rc0 + sum0;  l1 = l1*rc1 + sum1;
        m0 = m0n;  m1 = m1n;
#pragma unroll
        for (int t = 0; t < 16; t++) {
            o[t][0] *= rc0; o[t][1] *= rc0; o[t][2] *= rc1; o[t][3] *= rc1;
        }

#pragma unroll
        for (int kk = 0; kk < 4; kk++) {
            uint32_t ah[4];
            ah[0] = packh2(s[2*kk][0],   s[2*kk][1]);
            ah[1] = packh2(s[2*kk][2],   s[2*kk][3]);
            ah[2] = packh2(s[2*kk+1][0], s[2*kk+1][1]);
            ah[3] = packh2(s[2*kk+1][2], s[2*kk+1][3]);
#pragma unroll
            for (int dg = 0; dg < 8; dg++) {
                uint32_t vf[4];
                LDSM4T(vf, Vs + (size_t)(kk*16 + (lane & 15))*AT_STR + dg*16 + (lane >> 4)*8);
                MMAH(o[2*dg],   ah, vf[0], vf[1]);
                MMAH(o[2*dg+1], ah, vf[2], vf[3]);
            }
        }
    }

    float inv0 = 1.f / l0, inv1 = 1.f / l1;
#pragma unroll
    for (int t = 0; t < 16; t++) {
        size_t ro = base + (size_t)(qt*64 + warp*16 + (lane >> 2))*2048 + t*8 + (lane & 3)*2;
        *(uint32_t*)(atd + ro)          = packh2(o[t][0]*inv0, o[t][1]*inv0);
        *(uint32_t*)(atd + ro + 8*2048) = packh2(o[t][2]*inv1, o[t][3]*inv1);
    }
}

// ================= memory update: U = sig(K)^T V over HALF segments ==============
#define MU_KSTR 72
#define MU_KTILE (128*MU_KSTR)
#define MU_VSTR 136
#define MU_VTILE (64*MU_VSTR)
#define MEMUPD_SMEM ((MU_KTILE + MU_VTILE) * 2)

__global__ void __launch_bounds__(256)
memupd_mma_kernel(const __half* __restrict__ k, const __half* __restrict__ v,
                  float* __restrict__ U2, float* __restrict__ zU2)
{
    extern __shared__ __half sm[];
    __half* sK = sm;
    __half* sV = sm + MU_KTILE;
    __shared__ float zsm[128];

    int hseg = blockIdx.x & 15, bhx = blockIdx.x >> 4;
    int b = bhx >> 4, h = bhx & 15;
    int tid = threadIdx.x, warp = tid >> 5, lane = tid & 31;
    int wm = warp >> 1, wn = warp & 1;
    size_t base = ((size_t)(b*S_ + hseg*256) * H_ + h) * DK_;

    if (tid < 128) zsm[tid] = 0.f;

    float acc[2][8][4];
#pragma unroll
    for (int i = 0; i < 2; i++)
#pragma unroll
        for (int j = 0; j < 8; j++)
#pragma unroll
            for (int t = 0; t < 4; t++) acc[i][j][t] = 0.f;

    for (int st = 0; st < 4; st++) {
        int s0 = st * 64;
#pragma unroll
        for (int it = 0; it < 16; it++) {
            int e = it*256 + tid, s = e >> 6, c2 = e & 63;
            size_t go = base + (size_t)(s0 + s)*2048 + 2*c2;
            __half2 h2 = *(const __half2*)(k + go);
            sK[(2*c2)  *MU_KSTR + s] = __float2half_rn(elu1(__low2float(h2)));
            sK[(2*c2+1)*MU_KSTR + s] = __float2half_rn(elu1(__high2float(h2)));
        }
#pragma unroll
        for (int it = 0; it < 4; it++) {
            int e = it*256 + tid, r = e >> 4, c8 = (e & 15) << 3;
            size_t go = base + (size_t)(s0 + r)*2048 + c8;
            *(uint4*)(sV + r*MU_VSTR + c8) = *(const uint4*)(v + go);
        }
        __syncthreads();

        if (tid < 128) {
            float zz = 0.f;
#pragma unroll 4
            for (int s = 0; s < 64; s++) zz += __half2float(sK[tid*MU_KSTR + s]);
            zsm[tid] += zz;
        }

#pragma unroll
        for (int kk = 0; kk < 4; kk++) {
            uint32_t a[2][4];
#pragma unroll
            for (int mi = 0; mi < 2; mi++)
                LDSM4(a[mi], sK + (size_t)(wm*32 + mi*16 + (lane & 15))*MU_KSTR + kk*16 + (lane >> 4)*8);
#pragma unroll
            for (int ng = 0; ng < 4; ng++) {
                uint32_t bb[4];
                LDSM4T(bb, sV + (size_t)(kk*16 + (lane & 15))*MU_VSTR + wn*64 + ng*16 + (lane >> 4)*8);
#pragma unroll
                for (int mi = 0; mi < 2; mi++) {
                    MMAH(acc[mi][2*ng],   a[mi], bb[0], bb[1]);
                    MMAH(acc[mi][2*ng+1], a[mi], bb[2], bb[3]);
                }
            }
        }
        __syncthreads();
    }

    size_t ob = (size_t)blockIdx.x * (DK_*DV_);
#pragma unroll
    for (int mi = 0; mi < 2; mi++)
#pragma unroll
        for (int ni = 0; ni < 8; ni++) {
            int col = wn*64 + ni*8 + (lane & 3)*2;
#pragma unroll
            for (int hh = 0; hh < 2; hh++) {
                int row = wm*32 + mi*16 + (lane >> 2) + hh*8;
                float2 w; w.x = acc[mi][ni][hh*2]; w.y = acc[mi][ni][hh*2+1];
                *(float2*)(U2 + ob + (size_t)row*128 + col) = w;
            }
        }
    if (tid < 128) zU2[(size_t)blockIdx.x*128 + tid] = zsm[tid];
}

// ---------------- exclusive prefix over segments (widened) ----------------------
// grid (32 bh, 8 slices); slice y handles idx in [y*2048, (y+1)*2048)
__global__ void __launch_bounds__(256)
prefix_kernel(const float* __restrict__ U2, const float* __restrict__ zU2,
              float* __restrict__ Mem, float* __restrict__ Z)
{
    int bh = blockIdx.x, sl = blockIdx.y, tid = threadIdx.x;
    for (int idx = sl*2048 + tid; idx < (sl+1)*2048; idx += 256) {
        float run = 0.f;
#pragma unroll
        for (int sg = 0; sg < NSEG_; sg++) {
            Mem[((size_t)(bh*NSEG_ + sg)) * (DK_*DV_) + idx] = run;
            run += U2[((size_t)(bh*16 + 2*sg))   * (DK_*DV_) + idx]
                 + U2[((size_t)(bh*16 + 2*sg+1)) * (DK_*DV_) + idx];
        }
    }
    if (sl == 0 && tid < 128) {
        float run = 1.f / 128.f;
#pragma unroll
        for (int sg = 0; sg < NSEG_; sg++) {
            Z[(size_t)(bh*NSEG_ + sg) * 128 + tid] = run;
            run += zU2[(size_t)(bh*16 + 2*sg)   * 128 + tid]
                 + zU2[(size_t)(bh*16 + 2*sg+1) * 128 + tid];
        }
    }
}

// ================= retrieval + gate combine (fp16 mma) ===========================
#define RT_STR 136
#define RT_TILE (128*RT_STR)
#define RETR_SMEM (2 * RT_TILE * 2)

__global__ void __launch_bounds__(256)
retrieve_mma_kernel(const __half* __restrict__ q, const float* __restrict__ Mem,
                    const float* __restrict__ Z, const float* __restrict__ betas,
                    const __half* __restrict__ atd, __half* __restrict__ at)
{
    extern __shared__ __half sm[];
    __half* Mh = sm;
    __half* Sh = sm + RT_TILE;
    __shared__ float den[128], zz[128], gate[128], denp[256];

    int seg = blockIdx.x & 7, bhx = blockIdx.x >> 3;
    int b = bhx >> 4, h = bhx & 15;
    int tid = threadIdx.x, warp = tid >> 5, lane = tid & 31;
    size_t base = ((size_t)(b*S_ + seg*SEG_) * H_ + h) * DK_;
    size_t mb = (size_t)blockIdx.x * 16384;

    if (tid < 128) {
        gate[tid] = 1.f / (1.f + __expf(-betas[h*128 + tid]));
        zz[tid]   = Z[(size_t)blockIdx.x*128 + tid];
    }
#pragma unroll
    for (int it = 0; it < 16; it++) {
        int e = it*256 + tid, r = e >> 5, c4 = (e & 31) << 2;
        float4 v = *(const float4*)(Mem + mb + (size_t)r*128 + c4);
        *(__half2*)(Mh + r*RT_STR + c4)     = __floats2half2_rn(v.x, v.y);
        *(__half2*)(Mh + r*RT_STR + c4 + 2) = __floats2half2_rn(v.z, v.w);
    }
    __syncthreads();

    for (int ch = 0; ch < 4; ch++) {
        int s0 = ch * 128;
#pragma unroll
        for (int it = 0; it < 32; it++) {
            int e = it*256 + tid, s = e >> 6, c2 = e & 63;
            size_t go = base + (size_t)(s0 + s)*2048 + 2*c2;
            __half2 h2 = *(const __half2*)(q + go);
            *(__half2*)(Sh + s*RT_STR + 2*c2) =
                __floats2half2_rn(elu1(__low2float(h2)), elu1(__high2float(h2)));
        }
        __syncthreads();
        {
            int r = tid >> 1, hf = tid & 1;
            float d = 0.f;
#pragma unroll 4
            for (int dk = hf*64; dk < hf*64 + 64; dk++)
                d += __half2float(Sh[r*RT_STR + dk]) * zz[dk];
            denp[tid] = d;
        }
        __syncthreads();
        if (tid < 128) den[tid] = denp[2*tid] + denp[2*tid+1];
        __syncthreads();

        float o[16][4];
#pragma unroll
        for (int t = 0; t < 16; t++)
#pragma unroll
            for (int j = 0; j < 4; j++) o[t][j] = 0.f;

#pragma unroll
        for (int kk = 0; kk < 8; kk++) {
            uint32_t qa[4];
            LDSM4(qa, Sh + (size_t)(warp*16 + (lane & 15))*RT_STR + kk*16 + (lane >> 4)*8);
#pragma unroll
            for (int ng = 0; ng < 8; ng++) {
                uint32_t mh4[4];
                LDSM4T(mh4, Mh + (size_t)(kk*16 + (lane & 15))*RT_STR + ng*16 + (lane >> 4)*8);
                MMAH(o[2*ng],   qa, mh4[0], mh4[1]);
                MMAH(o[2*ng+1], qa, mh4[2], mh4[3]);
            }
        }

        float inv0 = 1.f / den[warp*16 + (lane >> 2)];
        float inv1 = 1.f / den[warp*16 + (lane >> 2) + 8];
#pragma unroll
        for (int t = 0; t < 16; t++) {
            int col = t*8 + (lane & 3)*2;
            float g0 = gate[col], g1 = gate[col+1];
            size_t ro = base + (size_t)(s0 + warp*16 + (lane >> 2))*2048 + col;
            __half2 d0 = *(const __half2*)(atd + ro);
            __half2 d1 = *(const __half2*)(atd + ro + 8*2048);
            float v0 = g0*(o[t][0]*inv0) + (1.f - g0)*__low2float(d0);
            float v1 = g1*(o[t][1]*inv0) + (1.f - g1)*__high2float(d0);
            float v2 = g0*(o[t][2]*inv1) + (1.f - g0)*__low2float(d1);
            float v3 = g1*(o[t][3]*inv1) + (1.f - g1)*__high2float(d1);
            *(uint32_t*)(at + ro)          = packh2(v0, v1);
            *(uint32_t*)(at + ro + 8*2048) = packh2(v2, v3);
        }
        __syncthreads();
    }
}

// ---------------- LayerNorm -----------------------------------------------------
__global__ void __launch_bounds__(256)
ln_kernel(const float* __restrict__ y, const float* __restrict__ gg,
          const float* __restrict__ bb, float* __restrict__ out)
{
    size_t row = blockIdx.x;
    const float* p = y + row * D_;
    int tid = threadIdx.x;
    float4 v0 = *(const float4*)(p + tid*8);
    float4 v1 = *(const float4*)(p + tid*8 + 4);
    float s  = v0.x+v0.y+v0.z+v0.w + v1.x+v1.y+v1.z+v1.w;
    float s2 = v0.x*v0.x+v0.y*v0.y+v0.z*v0.z+v0.w*v0.w
             + v1.x*v1.x+v1.y*v1.y+v1.z*v1.z+v1.w*v1.w;
#pragma unroll
    for (int o = 16; o >= 1; o >>= 1) {
        s  += __shfl_xor_sync(0xffffffffu, s, o);
        s2 += __shfl_xor_sync(0xffffffffu, s2, o);
    }
    __shared__ float red[16];
    __shared__ float stat[2];
    int warp = tid >> 5, lane = tid & 31;
    if (lane == 0) { red[warp] = s; red[warp + 8] = s2; }
    __syncthreads();
    if (tid == 0) {
        float S = 0.f, S2 = 0.f;
#pragma unroll
        for (int w = 0; w < 8; w++) { S += red[w]; S2 += red[w + 8]; }
        float mean = S / (float)D_;
        float var  = S2 / (float)D_ - mean*mean;
        stat[0] = mean;
        stat[1] = rsqrtf(var + 1e-5f);
    }
    __syncthreads();
    float mean = stat[0], inv = stat[1];
    float4 g0 = *(const float4*)(gg + tid*8), g1 = *(const float4*)(gg + tid*8 + 4);
    float4 b0 = *(const float4*)(bb + tid*8), b1 = *(const float4*)(bb + tid*8 + 4);
    float4 o0, o1;
    o0.x = (v0.x-mean)*inv*g0.x + b0.x; o0.y = (v0.y-mean)*inv*g0.y + b0.y;
    o0.z = (v0.z-mean)*inv*g0.z + b0.z; o0.w = (v0.w-mean)*inv*g0.w + b0.w;
    o1.x = (v1.x-mean)*inv*g1.x + b1.x; o1.y = (v1.y-mean)*inv*g1.y + b1.y;
    o1.z = (v1.z-mean)*inv*g1.z + b1.z; o1.w = (v1.w-mean)*inv*g1.w + b1.w;
    *(float4*)(out + row*D_ + tid*8)     = o0;
    *(float4*)(out + row*D_ + tid*8 + 4) = o1;
}

// ---------------- launch --------------------------------------------------------
static inline void cvt_launch(const float* src, __half* dst, size_t nelems)
{
    int nq = (int)(nelems / 4);
    cvt_kernel<<<(nq + 255)/256, 256>>>((const float4*)src, (__half2*)dst, nq);
}

extern "C" void kernel_launch(void* const* d_in, const int* in_sizes, int n_in,
                              void* d_out, int out_size)
{
    const float* x     = (const float*)d_in[0];
    const float* Wq    = (const float*)d_in[1];
    const float* Wk    = (const float*)d_in[2];
    const float* Wv    = (const float*)d_in[3];
    const float* Wo    = (const float*)d_in[4];
    const float* betas = (const float*)d_in[5];
    const float* W1    = (const float*)d_in[6];
    const float* b1    = (const float*)d_in[7];
    const float* W2    = (const float*)d_in[8];
    const float* b2    = (const float*)d_in[9];
    const float* ln_g  = (const float*)d_in[10];
    const float* ln_b  = (const float*)d_in[11];
    float* out = (float*)d_out;

    float *y_, *U2_, *zU2_, *mem_, *z_;
    cudaGetSymbolAddress((void**)&y_,   g_y);
    cudaGetSymbolAddress((void**)&U2_,  g_U2);
    cudaGetSymbolAddress((void**)&zU2_, g_zU2);
    cudaGetSymbolAddress((void**)&mem_, g_mem);
    cudaGetSymbolAddress((void**)&z_,   g_z);

    __half *xh,*wq,*wk,*wv,*wo,*w1,*w2,*qh,*kh,*vh,*atd,*at,*ao,*hh;
    cudaGetSymbolAddress((void**)&xh,  g_x);
    cudaGetSymbolAddress((void**)&wq,  g_wq);
    cudaGetSymbolAddress((void**)&wk,  g_wk);
    cudaGetSymbolAddress((void**)&wv,  g_wv);
    cudaGetSymbolAddress((void**)&wo,  g_wo);
    cudaGetSymbolAddress((void**)&w1,  g_w1);
    cudaGetSymbolAddress((void**)&w2,  g_w2);
    cudaGetSymbolAddress((void**)&qh,  g_q);
    cudaGetSymbolAddress((void**)&kh,  g_k);
    cudaGetSymbolAddress((void**)&vh,  g_v);
    cudaGetSymbolAddress((void**)&atd, g_atd);
    cudaGetSymbolAddress((void**)&at,  g_at);
    cudaGetSymbolAddress((void**)&ao,  g_ao);
    cudaGetSymbolAddress((void**)&hh,  g_hh);

    cudaFuncSetAttribute(hgemm_kernel,
        cudaFuncAttributeMaxDynamicSharedMemorySize, HG_SMEM);
    cudaFuncSetAttribute(hgemm_qkv_kernel,
        cudaFuncAttributeMaxDynamicSharedMemorySize, HG_SMEM);
    cudaFuncSetAttribute(attn_mma_kernel,
        cudaFuncAttributeMaxDynamicSharedMemorySize, ATTN_SMEM_BYTES);
    cudaFuncSetAttribute(memupd_mma_kernel,
        cudaFuncAttributeMaxDynamicSharedMemorySize, MEMUPD_SMEM);
    cudaFuncSetAttribute(retrieve_mma_kernel,
        cudaFuncAttributeMaxDynamicSharedMemorySize, RETR_SMEM);

    dim3 gProj(D_/128, M_/128);          // (16, 64)
    dim3 gQkv (D_/128, M_/128, 3);       // (16, 64, 3)
    dim3 gMlp1(DH_/128, M_/128);         // (64, 64)

    // 0: cvt x; 1: cvt QKV weights; 2: cvt Wo/W1/W2; 3: merged QKV GEMM;
    // 4: memupd; 5: attn (ncu -s 5 target)
    cvt_launch(x, xh, (size_t)M_ * D_);                                     // 0
    {
        int nq = (int)((size_t)D_ * D_ / 4);
        cvt3_kernel<<<dim3((nq + 255)/256, 3), 256>>>(                      // 1
            (const float4*)Wq, (const float4*)Wk, (const float4*)Wv,
            (__half2*)wq, (__half2*)wk, (__half2*)wv, nq, nq, nq);
    }
    {
        int n0 = (int)((size_t)D_ * D_  / 4);   // Wo: 1M quads
        int n1 = (int)((size_t)D_ * DH_ / 4);   // W1: 4M quads
        int n2 = (int)((size_t)DH_ * D_ / 4);   // W2: 4M quads
        int nmax = n1;
        cvt3_kernel<<<dim3((nmax + 255)/256, 3), 256>>>(                    // 2
            (const float4*)Wo, (const float4*)W1, (const float4*)W2,
            (__half2*)wo, (__half2*)w1, (__half2*)w2, n0, n1, n2);
    }
    hgemm_qkv_kernel<<<gQkv, 256, HG_SMEM>>>(xh, wq, wk, wv, qh, kh, vh);   // 3

    memupd_mma_kernel<<<512, 256, MEMUPD_SMEM>>>(kh, vh, U2_, zU2_);        // 4
    attn_mma_kernel<<<dim3(8, 8, 32), 128, ATTN_SMEM_BYTES>>>(qh, kh, vh, atd); // 5
    prefix_kernel<<<dim3(32, 8), 256>>>(U2_, zU2_, mem_, z_);               // 6
    retrieve_mma_kernel<<<256, 256, RETR_SMEM>>>(qh, mem_, z_, betas, atd, at); // 7

    hgemm_kernel<<<gProj, 256, HG_SMEM>>>(at, wo, D_, D_, nullptr, 0, nullptr, nullptr, ao); // 8
    hgemm_kernel<<<gMlp1, 256, HG_SMEM>>>(ao, w1, D_, DH_, b1, 1, nullptr, nullptr, hh);     // 9
    hgemm_kernel<<<gProj, 256, HG_SMEM>>>(hh, w2, DH_, D_, b2, 0, x, y_, nullptr);           // 10
    ln_kernel<<<M_, 256>>>(y_, ln_g, ln_b, out);                                             // 11
}